// round 1
// baseline (speedup 1.0000x reference)
#include <cuda_runtime.h>
#include <math.h>

#define Himg 56
#define Wimg 56
#define WS 7
#define SHIFT 3
#define HEADS 4
#define DIM 128
#define NTOK 49
#define BIMG 64
#define NWIN 4096           // 64 imgs * 64 windows
#define MTOK 200704         // NWIN * NTOK  (== 64*3136)
#define HD 32

// ---------------- scratch (static device globals; no allocation) -------------
__device__ float g_xw  [(size_t)MTOK * DIM];       // LN1 + shift + partition
__device__ float g_qkv [(size_t)MTOK * 3 * DIM];   // qkv
__device__ float g_attn[(size_t)MTOK * DIM];       // attention output (window layout)
__device__ float g_proj[(size_t)MTOK * DIM];       // proj output (window layout)
__device__ float g_x2  [(size_t)MTOK * DIM];       // residual 1 (image layout)
__device__ float g_ln2 [(size_t)MTOK * DIM];       // LN2 output
__device__ float g_h   [(size_t)MTOK * 4 * DIM];   // MLP hidden

// ---------------- kernel 1: LN1 + cyclic shift + window partition ------------
__global__ void k_ln_shift_part(const float* __restrict__ x,
                                const float* __restrict__ gw,
                                const float* __restrict__ gb) {
    __shared__ float s1[4], s2[4];
    int t = blockIdx.x;                 // window-token index
    int win = t / NTOK, n = t - win * NTOK;
    int bimg = win >> 6, wi = win & 63;
    int rr = (wi >> 3) * WS + n / WS;   // shifted-frame row
    int cc = (wi & 7)  * WS + n % WS;   // shifted-frame col
    int r = rr + SHIFT; if (r >= Himg) r -= Himg;   // roll(-SHIFT): out[i]=x[i+SHIFT]
    int c = cc + SHIFT; if (c >= Wimg) c -= Wimg;
    int ch = threadIdx.x;
    float v = x[((size_t)bimg * 3136 + r * 56 + c) * DIM + ch];
    float sv = v, sq = v * v;
    #pragma unroll
    for (int o = 16; o > 0; o >>= 1) {
        sv += __shfl_down_sync(0xffffffffu, sv, o);
        sq += __shfl_down_sync(0xffffffffu, sq, o);
    }
    if ((ch & 31) == 0) { s1[ch >> 5] = sv; s2[ch >> 5] = sq; }
    __syncthreads();
    float mean = (s1[0] + s1[1] + s1[2] + s1[3]) * (1.0f / 128.0f);
    float var  = (s2[0] + s2[1] + s2[2] + s2[3]) * (1.0f / 128.0f) - mean * mean;
    float inv  = rsqrtf(var + 1e-5f);
    g_xw[(size_t)t * DIM + ch] = (v - mean) * inv * gw[ch] + gb[ch];
}

// ---------------- generic 128x128x8 fp32 SGEMM with epilogue -----------------
// EPI: 0 = +bias ; 1 = +bias then exact GELU ; 2 = +bias +residual
template <int EPI>
__global__ void __launch_bounds__(256, 2)
k_sgemm(const float* __restrict__ A, const float* __restrict__ B,
        const float* __restrict__ bias, const float* __restrict__ res,
        float* __restrict__ C, int M, int N, int K) {
    __shared__ float As[8][128];
    __shared__ float Bs[8][128];
    int tid = threadIdx.x;
    int bm = blockIdx.y, bn = blockIdx.x;
    int arow = tid >> 1, acol = (tid & 1) << 2;
    int brow = tid >> 5, bcol = (tid & 31) << 2;
    const float* Ap = A + (size_t)(bm * 128 + arow) * K + acol;
    const float* Bp = B + (size_t)brow * N + bn * 128 + bcol;
    int ty = tid >> 4, tx = tid & 15;
    float acc[8][8];
    #pragma unroll
    for (int i = 0; i < 8; i++)
        #pragma unroll
        for (int j = 0; j < 8; j++) acc[i][j] = 0.0f;

    for (int kt = 0; kt < K; kt += 8) {
        float4 av = *(const float4*)(Ap + kt);
        float4 bv = *(const float4*)(Bp + (size_t)kt * N);
        __syncthreads();
        As[acol + 0][arow] = av.x; As[acol + 1][arow] = av.y;
        As[acol + 2][arow] = av.z; As[acol + 3][arow] = av.w;
        *(float4*)&Bs[brow][bcol] = bv;
        __syncthreads();
        #pragma unroll
        for (int kk = 0; kk < 8; kk++) {
            float a[8], b[8];
            #pragma unroll
            for (int i = 0; i < 8; i++) a[i] = As[kk][ty * 8 + i];
            #pragma unroll
            for (int j = 0; j < 8; j++) b[j] = Bs[kk][tx * 8 + j];
            #pragma unroll
            for (int i = 0; i < 8; i++)
                #pragma unroll
                for (int j = 0; j < 8; j++) acc[i][j] += a[i] * b[j];
        }
    }

    int row0 = bm * 128 + ty * 8;
    int col0 = bn * 128 + tx * 8;
    #pragma unroll
    for (int i = 0; i < 8; i++) {
        float out[8];
        #pragma unroll
        for (int j = 0; j < 8; j++) {
            float v = acc[i][j] + bias[col0 + j];
            if (EPI == 1) v = 0.5f * v * (1.0f + erff(v * 0.7071067811865476f));
            if (EPI == 2) v += res[(size_t)(row0 + i) * N + col0 + j];
            out[j] = v;
        }
        float4* cp = (float4*)(C + (size_t)(row0 + i) * N + col0);
        cp[0] = make_float4(out[0], out[1], out[2], out[3]);
        cp[1] = make_float4(out[4], out[5], out[6], out[7]);
    }
}

// ---------------- kernel 3: windowed attention per (window, head) ------------
__device__ __forceinline__ int region_of(int p) {
    return p < Himg - WS ? 0 : (p < Himg - SHIFT ? 1 : 2);
}

__global__ void k_attn(const float* __restrict__ qkv,
                       const float* __restrict__ rpb) {
    __shared__ float q[NTOK * HD], k[NTOK * HD], v[NTOK * HD], p[NTOK * NTOK];
    int w = blockIdx.x, h = blockIdx.y;
    int tid = threadIdx.x;                              // 128 threads
    for (int i = tid; i < NTOK * HD; i += 128) {
        int t = i / HD, d = i - t * HD;
        const float* base = qkv + (size_t)(w * NTOK + t) * (3 * DIM) + h * HD + d;
        q[i] = base[0];
        k[i] = base[DIM];
        v[i] = base[2 * DIM];
    }
    __syncthreads();
    int wi = w & 63, wy = wi >> 3, wx = wi & 7;
    const float scale = 0.17677669529663687f;           // 1/sqrt(32)
    for (int i = tid; i < NTOK * NTOK; i += 128) {
        int n = i / NTOK, m = i - n * NTOK;
        float s = 0.0f;
        #pragma unroll
        for (int d = 0; d < HD; d++) s += q[n * HD + d] * k[m * HD + d];
        int iy = n / WS, ix = n - iy * WS;
        int jy = m / WS, jx = m - jy * WS;
        int rel = (iy - jy + WS - 1) * (2 * WS - 1) + (ix - jx + WS - 1);
        s = s * scale + rpb[rel * HEADS + h];
        int ln = region_of(wy * WS + iy) * 3 + region_of(wx * WS + ix);
        int lm = region_of(wy * WS + jy) * 3 + region_of(wx * WS + jx);
        if (ln != lm) s -= 100.0f;
        p[i] = s;
    }
    __syncthreads();
    if (tid < NTOK) {
        float mx = -1e30f;
        #pragma unroll 7
        for (int m = 0; m < NTOK; m++) mx = fmaxf(mx, p[tid * NTOK + m]);
        float sum = 0.0f;
        #pragma unroll 7
        for (int m = 0; m < NTOK; m++) {
            float e = __expf(p[tid * NTOK + m] - mx);
            p[tid * NTOK + m] = e;
            sum += e;
        }
        float inv = 1.0f / sum;
        #pragma unroll 7
        for (int m = 0; m < NTOK; m++) p[tid * NTOK + m] *= inv;
    }
    __syncthreads();
    for (int i = tid; i < NTOK * HD; i += 128) {
        int n = i / HD, d = i - n * HD;
        float s = 0.0f;
        #pragma unroll 7
        for (int m = 0; m < NTOK; m++) s += p[n * NTOK + m] * v[m * HD + d];
        g_attn[(size_t)(w * NTOK + n) * DIM + h * HD + d] = s;
    }
}

// --------- kernel 5: window reverse + un-shift + residual + LN2 --------------
__global__ void k_rev_res_ln2(const float* __restrict__ x,
                              const float* __restrict__ gw,
                              const float* __restrict__ gb) {
    __shared__ float s1[4], s2[4];
    int t = blockIdx.x;                 // image-layout token: b*3136 + r*56 + c
    int bimg = t / 3136, rc = t - bimg * 3136;
    int r = rc / 56, c = rc - r * 56;
    int rr = r - SHIFT; if (rr < 0) rr += Himg;   // roll(+SHIFT) reverse
    int cc = c - SHIFT; if (cc < 0) cc += Wimg;
    int w = bimg * 64 + (rr / WS) * 8 + (cc / WS);
    int n = (rr % WS) * WS + (cc % WS);
    int ch = threadIdx.x;
    float v = x[(size_t)t * DIM + ch] + g_proj[(size_t)(w * NTOK + n) * DIM + ch];
    g_x2[(size_t)t * DIM + ch] = v;
    float sv = v, sq = v * v;
    #pragma unroll
    for (int o = 16; o > 0; o >>= 1) {
        sv += __shfl_down_sync(0xffffffffu, sv, o);
        sq += __shfl_down_sync(0xffffffffu, sq, o);
    }
    if ((ch & 31) == 0) { s1[ch >> 5] = sv; s2[ch >> 5] = sq; }
    __syncthreads();
    float mean = (s1[0] + s1[1] + s1[2] + s1[3]) * (1.0f / 128.0f);
    float var  = (s2[0] + s2[1] + s2[2] + s2[3]) * (1.0f / 128.0f) - mean * mean;
    float inv  = rsqrtf(var + 1e-5f);
    g_ln2[(size_t)t * DIM + ch] = (v - mean) * inv * gw[ch] + gb[ch];
}

// ------------------------------- launcher ------------------------------------
extern "C" void kernel_launch(void* const* d_in, const int* in_sizes, int n_in,
                              void* d_out, int out_size) {
    const float* x      = (const float*)d_in[0];
    const float* qkv_w  = (const float*)d_in[1];
    const float* qkv_b  = (const float*)d_in[2];
    const float* proj_w = (const float*)d_in[3];
    const float* proj_b = (const float*)d_in[4];
    const float* rpb    = (const float*)d_in[5];
    const float* n1w    = (const float*)d_in[6];
    const float* n1b    = (const float*)d_in[7];
    const float* n2w    = (const float*)d_in[8];
    const float* n2b    = (const float*)d_in[9];
    const float* w1     = (const float*)d_in[10];
    const float* b1     = (const float*)d_in[11];
    const float* w2     = (const float*)d_in[12];
    const float* b2     = (const float*)d_in[13];
    float* out = (float*)d_out;

    float *p_xw, *p_qkv, *p_attn, *p_proj, *p_x2, *p_ln2, *p_h;
    cudaGetSymbolAddress((void**)&p_xw,   g_xw);
    cudaGetSymbolAddress((void**)&p_qkv,  g_qkv);
    cudaGetSymbolAddress((void**)&p_attn, g_attn);
    cudaGetSymbolAddress((void**)&p_proj, g_proj);
    cudaGetSymbolAddress((void**)&p_x2,   g_x2);
    cudaGetSymbolAddress((void**)&p_ln2,  g_ln2);
    cudaGetSymbolAddress((void**)&p_h,    g_h);

    // 1) LN1 + shift + window partition
    k_ln_shift_part<<<MTOK, 128>>>(x, n1w, n1b);

    // 2) QKV GEMM: [200704,128] @ [128,384] + bias
    k_sgemm<0><<<dim3(3, MTOK / 128), 256>>>(p_xw, qkv_w, qkv_b, nullptr,
                                             p_qkv, MTOK, 3 * DIM, DIM);

    // 3) windowed attention
    k_attn<<<dim3(NWIN, HEADS), 128>>>(p_qkv, rpb);

    // 4) proj GEMM: [200704,128] @ [128,128] + bias
    k_sgemm<0><<<dim3(1, MTOK / 128), 256>>>(p_attn, proj_w, proj_b, nullptr,
                                             p_proj, MTOK, DIM, DIM);

    // 5) window reverse + un-shift + residual + LN2
    k_rev_res_ln2<<<MTOK, 128>>>(x, n2w, n2b);

    // 6) MLP1: [200704,128] @ [128,512] + bias, exact GELU
    k_sgemm<1><<<dim3(4, MTOK / 128), 256>>>(p_ln2, w1, b1, nullptr,
                                             p_h, MTOK, 4 * DIM, DIM);

    // 7) MLP2: [200704,512] @ [512,128] + bias + residual -> d_out
    k_sgemm<2><<<dim3(1, MTOK / 128), 256>>>(p_h, w2, b2, p_x2,
                                             out, MTOK, DIM, 4 * DIM);
}

// round 3
// speedup vs baseline: 1.4934x; 1.4934x over previous
#include <cuda_runtime.h>
#include <math.h>
#include <stdint.h>

#define Himg 56
#define Wimg 56
#define WS 7
#define SHIFT 3
#define HEADS 4
#define DIM 128
#define NTOK 49
#define NWIN 4096           // 64 imgs * 64 windows
#define MTOK 200704         // NWIN * NTOK
#define HD 32

// ---------------- scratch (static device globals; no allocation) -------------
__device__ float g_xw  [(size_t)MTOK * DIM];
__device__ float g_qkv [(size_t)MTOK * 3 * DIM];
__device__ float g_attn[(size_t)MTOK * DIM];
__device__ float g_proj[(size_t)MTOK * DIM];
__device__ float g_x2  [(size_t)MTOK * DIM];
__device__ float g_ln2 [(size_t)MTOK * DIM];
__device__ float g_h   [(size_t)MTOK * 4 * DIM];
// transposed weights [N, K]
__device__ float g_wt_qkv [384 * 128];
__device__ float g_wt_proj[128 * 128];
__device__ float g_wt1    [512 * 128];
__device__ float g_wt2    [128 * 512];

__device__ __forceinline__ uint32_t f2tf32(float x) {
    uint32_t r;
    asm("cvt.rna.tf32.f32 %0, %1;" : "=r"(r) : "f"(x));
    return r;
}

// ---------------- kernel 1: LN1 + cyclic shift + window partition ------------
__global__ void k_ln_shift_part(const float* __restrict__ x,
                                const float* __restrict__ gw,
                                const float* __restrict__ gb) {
    __shared__ float s1[4], s2[4];
    int t = blockIdx.x;
    int win = t / NTOK, n = t - win * NTOK;
    int bimg = win >> 6, wi = win & 63;
    int rr = (wi >> 3) * WS + n / WS;
    int cc = (wi & 7)  * WS + n % WS;
    int r = rr + SHIFT; if (r >= Himg) r -= Himg;
    int c = cc + SHIFT; if (c >= Wimg) c -= Wimg;
    int ch = threadIdx.x;
    float v = x[((size_t)bimg * 3136 + r * 56 + c) * DIM + ch];
    float sv = v, sq = v * v;
    #pragma unroll
    for (int o = 16; o > 0; o >>= 1) {
        sv += __shfl_down_sync(0xffffffffu, sv, o);
        sq += __shfl_down_sync(0xffffffffu, sq, o);
    }
    if ((ch & 31) == 0) { s1[ch >> 5] = sv; s2[ch >> 5] = sq; }
    __syncthreads();
    float mean = (s1[0] + s1[1] + s1[2] + s1[3]) * (1.0f / 128.0f);
    float var  = (s2[0] + s2[1] + s2[2] + s2[3]) * (1.0f / 128.0f) - mean * mean;
    float inv  = rsqrtf(var + 1e-5f);
    g_xw[(size_t)t * DIM + ch] = (v - mean) * inv * gw[ch] + gb[ch];
}

// ---------------- weight transpose: W[K,N] -> WT[N,K] -------------------------
__global__ void k_transpose(const float* __restrict__ W, float* __restrict__ WT,
                            int Kd, int Nd) {
    int i = blockIdx.x * 256 + threadIdx.x;
    if (i < Kd * Nd) {
        int k = i / Nd, n = i - k * Nd;
        WT[(size_t)n * Kd + k] = W[i];
    }
}

// -------- tf32 HMMA GEMM: C[M,N] = A[M,K] @ BT[N,K]^T, 128x128 tile ----------
// EPI: 0 = +bias ; 1 = +bias, exact GELU ; 2 = +bias +residual
#define KC 32
template <int EPI>
__global__ void __launch_bounds__(256, 2)
k_mgemm(const float* __restrict__ A, const float* __restrict__ BT,
        const float* __restrict__ bias, const float* __restrict__ res,
        float* __restrict__ C, int K, int N) {
    __shared__ float sA[128][KC + 4];
    __shared__ float sB[128][KC + 4];
    int tid = threadIdx.x;
    int wid = tid >> 5, lane = tid & 31;
    int wm = wid & 3, wn = wid >> 2;          // warp grid 4(M) x 2(N)
    int m0 = blockIdx.y << 7, n0 = blockIdx.x << 7;
    int g = lane >> 2, cq = lane & 3;         // fragment coords

    float acc[2][8][4];
    #pragma unroll
    for (int i = 0; i < 2; i++)
        #pragma unroll
        for (int j = 0; j < 8; j++)
            #pragma unroll
            for (int q = 0; q < 4; q++) acc[i][j][q] = 0.0f;

    int lrow = tid >> 3;                      // 0..31
    int lcol = (tid & 7) << 2;                // 0,4,...,28

    for (int kc = 0; kc < K; kc += KC) {
        __syncthreads();
        #pragma unroll
        for (int it = 0; it < 4; it++) {
            int r = it * 32 + lrow;
            float4 av = *(const float4*)(A  + (size_t)(m0 + r) * K + kc + lcol);
            float4 bv = *(const float4*)(BT + (size_t)(n0 + r) * K + kc + lcol);
            uint32_t* da = (uint32_t*)&sA[r][lcol];
            uint32_t* db = (uint32_t*)&sB[r][lcol];
            da[0] = f2tf32(av.x); da[1] = f2tf32(av.y);
            da[2] = f2tf32(av.z); da[3] = f2tf32(av.w);
            db[0] = f2tf32(bv.x); db[1] = f2tf32(bv.y);
            db[2] = f2tf32(bv.z); db[3] = f2tf32(bv.w);
        }
        __syncthreads();
        #pragma unroll
        for (int ks = 0; ks < KC; ks += 8) {
            uint32_t a[2][4], b[8][2];
            #pragma unroll
            for (int ma = 0; ma < 2; ma++) {
                int r = wm * 32 + ma * 16 + g;
                a[ma][0] = __float_as_uint(sA[r    ][ks + cq    ]);
                a[ma][1] = __float_as_uint(sA[r + 8][ks + cq    ]);
                a[ma][2] = __float_as_uint(sA[r    ][ks + cq + 4]);
                a[ma][3] = __float_as_uint(sA[r + 8][ks + cq + 4]);
            }
            #pragma unroll
            for (int na = 0; na < 8; na++) {
                int cl = wn * 64 + na * 8 + g;
                b[na][0] = __float_as_uint(sB[cl][ks + cq    ]);
                b[na][1] = __float_as_uint(sB[cl][ks + cq + 4]);
            }
            #pragma unroll
            for (int ma = 0; ma < 2; ma++)
                #pragma unroll
                for (int na = 0; na < 8; na++)
                    asm volatile(
                        "mma.sync.aligned.m16n8k8.row.col.f32.tf32.tf32.f32 "
                        "{%0,%1,%2,%3}, {%4,%5,%6,%7}, {%8,%9}, {%0,%1,%2,%3};"
                        : "+f"(acc[ma][na][0]), "+f"(acc[ma][na][1]),
                          "+f"(acc[ma][na][2]), "+f"(acc[ma][na][3])
                        : "r"(a[ma][0]), "r"(a[ma][1]), "r"(a[ma][2]), "r"(a[ma][3]),
                          "r"(b[na][0]), "r"(b[na][1]));
        }
    }

    // epilogue: acc[ma][na] tile at rows (wm*32+ma*16+g, +8), cols (wn*64+na*8+2cq, +1)
    #pragma unroll
    for (int ma = 0; ma < 2; ma++) {
        int r0 = m0 + wm * 32 + ma * 16 + g;
        #pragma unroll
        for (int na = 0; na < 8; na++) {
            int cb = n0 + wn * 64 + na * 8 + 2 * cq;
            float b0 = bias[cb], b1 = bias[cb + 1];
            float v0 = acc[ma][na][0] + b0;
            float v1 = acc[ma][na][1] + b1;
            float v2 = acc[ma][na][2] + b0;
            float v3 = acc[ma][na][3] + b1;
            if (EPI == 1) {
                v0 = 0.5f * v0 * (1.0f + erff(v0 * 0.7071067811865476f));
                v1 = 0.5f * v1 * (1.0f + erff(v1 * 0.7071067811865476f));
                v2 = 0.5f * v2 * (1.0f + erff(v2 * 0.7071067811865476f));
                v3 = 0.5f * v3 * (1.0f + erff(v3 * 0.7071067811865476f));
            }
            if (EPI == 2) {
                float2 r1v = *(const float2*)(res + (size_t)r0 * N + cb);
                float2 r2v = *(const float2*)(res + (size_t)(r0 + 8) * N + cb);
                v0 += r1v.x; v1 += r1v.y; v2 += r2v.x; v3 += r2v.y;
            }
            *(float2*)(C + (size_t)r0 * N + cb)       = make_float2(v0, v1);
            *(float2*)(C + (size_t)(r0 + 8) * N + cb) = make_float2(v2, v3);
        }
    }
}

// ---------------- kernel 3: windowed attention per (window, head) ------------
__device__ __forceinline__ int region_of(int p) {
    return p < Himg - WS ? 0 : (p < Himg - SHIFT ? 1 : 2);
}

__global__ void k_attn(const float* __restrict__ qkv,
                       const float* __restrict__ rpb) {
    __shared__ float q[NTOK * HD], k[NTOK * HD], v[NTOK * HD], p[NTOK * NTOK];
    int w = blockIdx.x, h = blockIdx.y;
    int tid = threadIdx.x;
    for (int i = tid; i < NTOK * HD; i += 128) {
        int t = i / HD, d = i - t * HD;
        const float* base = qkv + (size_t)(w * NTOK + t) * (3 * DIM) + h * HD + d;
        q[i] = base[0];
        k[i] = base[DIM];
        v[i] = base[2 * DIM];
    }
    __syncthreads();
    int wi = w & 63, wy = wi >> 3, wx = wi & 7;
    const float scale = 0.17677669529663687f;
    for (int i = tid; i < NTOK * NTOK; i += 128) {
        int n = i / NTOK, m = i - n * NTOK;
        float s = 0.0f;
        #pragma unroll
        for (int d = 0; d < HD; d++) s += q[n * HD + d] * k[m * HD + d];
        int iy = n / WS, ix = n - iy * WS;
        int jy = m / WS, jx = m - jy * WS;
        int rel = (iy - jy + WS - 1) * (2 * WS - 1) + (ix - jx + WS - 1);
        s = s * scale + rpb[rel * HEADS + h];
        int ln = region_of(wy * WS + iy) * 3 + region_of(wx * WS + ix);
        int lm = region_of(wy * WS + jy) * 3 + region_of(wx * WS + jx);
        if (ln != lm) s -= 100.0f;
        p[i] = s;
    }
    __syncthreads();
    if (tid < NTOK) {
        float mx = -1e30f;
        #pragma unroll 7
        for (int m = 0; m < NTOK; m++) mx = fmaxf(mx, p[tid * NTOK + m]);
        float sum = 0.0f;
        #pragma unroll 7
        for (int m = 0; m < NTOK; m++) {
            float e = __expf(p[tid * NTOK + m] - mx);
            p[tid * NTOK + m] = e;
            sum += e;
        }
        float inv = 1.0f / sum;
        #pragma unroll 7
        for (int m = 0; m < NTOK; m++) p[tid * NTOK + m] *= inv;
    }
    __syncthreads();
    for (int i = tid; i < NTOK * HD; i += 128) {
        int n = i / HD, d = i - n * HD;
        float s = 0.0f;
        #pragma unroll 7
        for (int m = 0; m < NTOK; m++) s += p[n * NTOK + m] * v[m * HD + d];
        g_attn[(size_t)(w * NTOK + n) * DIM + h * HD + d] = s;
    }
}

// --------- kernel 5: window reverse + un-shift + residual + LN2 --------------
__global__ void k_rev_res_ln2(const float* __restrict__ x,
                              const float* __restrict__ gw,
                              const float* __restrict__ gb) {
    __shared__ float s1[4], s2[4];
    int t = blockIdx.x;
    int bimg = t / 3136, rc = t - bimg * 3136;
    int r = rc / 56, c = rc - r * 56;
    int rr = r - SHIFT; if (rr < 0) rr += Himg;
    int cc = c - SHIFT; if (cc < 0) cc += Wimg;
    int w = bimg * 64 + (rr / WS) * 8 + (cc / WS);
    int n = (rr % WS) * WS + (cc % WS);
    int ch = threadIdx.x;
    float v = x[(size_t)t * DIM + ch] + g_proj[(size_t)(w * NTOK + n) * DIM + ch];
    g_x2[(size_t)t * DIM + ch] = v;
    float sv = v, sq = v * v;
    #pragma unroll
    for (int o = 16; o > 0; o >>= 1) {
        sv += __shfl_down_sync(0xffffffffu, sv, o);
        sq += __shfl_down_sync(0xffffffffu, sq, o);
    }
    if ((ch & 31) == 0) { s1[ch >> 5] = sv; s2[ch >> 5] = sq; }
    __syncthreads();
    float mean = (s1[0] + s1[1] + s1[2] + s1[3]) * (1.0f / 128.0f);
    float var  = (s2[0] + s2[1] + s2[2] + s2[3]) * (1.0f / 128.0f) - mean * mean;
    float inv  = rsqrtf(var + 1e-5f);
    g_ln2[(size_t)t * DIM + ch] = (v - mean) * inv * gw[ch] + gb[ch];
}

// ------------------------------- launcher ------------------------------------
extern "C" void kernel_launch(void* const* d_in, const int* in_sizes, int n_in,
                              void* d_out, int out_size) {
    const float* x      = (const float*)d_in[0];
    const float* qkv_w  = (const float*)d_in[1];
    const float* qkv_b  = (const float*)d_in[2];
    const float* proj_w = (const float*)d_in[3];
    const float* proj_b = (const float*)d_in[4];
    const float* rpb    = (const float*)d_in[5];
    const float* n1w    = (const float*)d_in[6];
    const float* n1b    = (const float*)d_in[7];
    const float* n2w    = (const float*)d_in[8];
    const float* n2b    = (const float*)d_in[9];
    const float* w1     = (const float*)d_in[10];
    const float* b1     = (const float*)d_in[11];
    const float* w2     = (const float*)d_in[12];
    const float* b2     = (const float*)d_in[13];
    float* out = (float*)d_out;

    float *p_xw, *p_qkv, *p_attn, *p_proj, *p_x2, *p_ln2, *p_h;
    float *p_wtq, *p_wtp, *p_wt1, *p_wt2;
    cudaGetSymbolAddress((void**)&p_xw,   g_xw);
    cudaGetSymbolAddress((void**)&p_qkv,  g_qkv);
    cudaGetSymbolAddress((void**)&p_attn, g_attn);
    cudaGetSymbolAddress((void**)&p_proj, g_proj);
    cudaGetSymbolAddress((void**)&p_x2,   g_x2);
    cudaGetSymbolAddress((void**)&p_ln2,  g_ln2);
    cudaGetSymbolAddress((void**)&p_h,    g_h);
    cudaGetSymbolAddress((void**)&p_wtq,  g_wt_qkv);
    cudaGetSymbolAddress((void**)&p_wtp,  g_wt_proj);
    cudaGetSymbolAddress((void**)&p_wt1,  g_wt1);
    cudaGetSymbolAddress((void**)&p_wt2,  g_wt2);

    // 0) weight transposes ([K,N] -> [N,K])
    k_transpose<<<(128*384 + 255) / 256, 256>>>(qkv_w,  p_wtq, 128, 384);
    k_transpose<<<(128*128 + 255) / 256, 256>>>(proj_w, p_wtp, 128, 128);
    k_transpose<<<(128*512 + 255) / 256, 256>>>(w1,     p_wt1, 128, 512);
    k_transpose<<<(512*128 + 255) / 256, 256>>>(w2,     p_wt2, 512, 128);

    // 1) LN1 + shift + window partition
    k_ln_shift_part<<<MTOK, 128>>>(x, n1w, n1b);

    // 2) QKV GEMM: [200704,128] @ [128,384] + bias
    k_mgemm<0><<<dim3(3, MTOK / 128), 256>>>(p_xw, p_wtq, qkv_b, nullptr, p_qkv, 128, 384);

    // 3) windowed attention
    k_attn<<<dim3(NWIN, HEADS), 128>>>(p_qkv, rpb);

    // 4) proj GEMM: [200704,128] @ [128,128] + bias
    k_mgemm<0><<<dim3(1, MTOK / 128), 256>>>(p_attn, p_wtp, proj_b, nullptr, p_proj, 128, 128);

    // 5) window reverse + un-shift + residual + LN2
    k_rev_res_ln2<<<MTOK, 128>>>(x, n2w, n2b);

    // 6) MLP1: [200704,128] @ [128,512] + bias, exact GELU
    k_mgemm<1><<<dim3(4, MTOK / 128), 256>>>(p_ln2, p_wt1, b1, nullptr, p_h, 128, 512);

    // 7) MLP2: [200704,512] @ [512,128] + bias + residual -> d_out
    k_mgemm<2><<<dim3(1, MTOK / 128), 256>>>(p_h, p_wt2, b2, p_x2, out, 512, 128);
}

// round 4
// speedup vs baseline: 2.4802x; 1.6608x over previous
#include <cuda_runtime.h>
#include <cuda_bf16.h>
#include <math.h>
#include <stdint.h>

#define Himg 56
#define Wimg 56
#define WS 7
#define SHIFT 3
#define HEADS 4
#define DIM 128
#define NTOK 49
#define NWIN 4096           // 64 imgs * 64 windows
#define MTOK 200704         // NWIN * NTOK
#define HD 32
#define QS 33               // padded row stride for attention smem

// ---------------- scratch (static device globals; no allocation) -------------
__device__ __nv_bfloat16 g_xw  [(size_t)MTOK * DIM];       // LN1 out (GEMM input)
__device__ float         g_qkv [(size_t)MTOK * 3 * DIM];   // qkv (fp32, attention input)
__device__ __nv_bfloat16 g_attn[(size_t)MTOK * DIM];       // attention out (GEMM input)
__device__ float         g_proj[(size_t)MTOK * DIM];       // proj out
__device__ float         g_x2  [(size_t)MTOK * DIM];       // residual 1
__device__ __nv_bfloat16 g_ln2 [(size_t)MTOK * DIM];       // LN2 out (GEMM input)
__device__ __nv_bfloat16 g_h   [(size_t)MTOK * 4 * DIM];   // MLP hidden (bf16)
// transposed weights [N, K] in bf16
__device__ __nv_bfloat16 g_wt_qkv [384 * 128];
__device__ __nv_bfloat16 g_wt_proj[128 * 128];
__device__ __nv_bfloat16 g_wt1    [512 * 128];
__device__ __nv_bfloat16 g_wt2    [128 * 512];

__device__ __forceinline__ uint32_t smem_u32(const void* p) {
    uint32_t a;
    asm("{ .reg .u64 t; cvta.to.shared.u64 t, %1; cvt.u32.u64 %0, t; }" : "=r"(a) : "l"(p));
    return a;
}
__device__ __forceinline__ void cpa16(uint32_t dst, const void* src) {
    asm volatile("cp.async.cg.shared.global [%0], [%1], 16;" :: "r"(dst), "l"(src));
}

// ---------------- kernel 1: LN1 + cyclic shift + window partition ------------
__global__ void k_ln_shift_part(const float* __restrict__ x,
                                const float* __restrict__ gw,
                                const float* __restrict__ gb) {
    __shared__ float s1[4], s2[4];
    int t = blockIdx.x;
    int win = t / NTOK, n = t - win * NTOK;
    int bimg = win >> 6, wi = win & 63;
    int rr = (wi >> 3) * WS + n / WS;
    int cc = (wi & 7)  * WS + n % WS;
    int r = rr + SHIFT; if (r >= Himg) r -= Himg;
    int c = cc + SHIFT; if (c >= Wimg) c -= Wimg;
    int ch = threadIdx.x;
    float v = x[((size_t)bimg * 3136 + r * 56 + c) * DIM + ch];
    float sv = v, sq = v * v;
    #pragma unroll
    for (int o = 16; o > 0; o >>= 1) {
        sv += __shfl_down_sync(0xffffffffu, sv, o);
        sq += __shfl_down_sync(0xffffffffu, sq, o);
    }
    if ((ch & 31) == 0) { s1[ch >> 5] = sv; s2[ch >> 5] = sq; }
    __syncthreads();
    float mean = (s1[0] + s1[1] + s1[2] + s1[3]) * (1.0f / 128.0f);
    float var  = (s2[0] + s2[1] + s2[2] + s2[3]) * (1.0f / 128.0f) - mean * mean;
    float inv  = rsqrtf(var + 1e-5f);
    g_xw[(size_t)t * DIM + ch] = __float2bfloat16((v - mean) * inv * gw[ch] + gb[ch]);
}

// ---------------- weight transpose: W[K,N] fp32 -> WT[N,K] bf16 ---------------
__global__ void k_transpose(const float* __restrict__ W, __nv_bfloat16* __restrict__ WT,
                            int Kd, int Nd) {
    int i = blockIdx.x * 256 + threadIdx.x;
    if (i < Kd * Nd) {
        int k = i / Nd, n = i - k * Nd;
        WT[(size_t)n * Kd + k] = __float2bfloat16(W[i]);
    }
}

// -------- bf16 HMMA GEMM: C[M,N] = A[M,K] @ BT[N,K]^T, 128x128 tile ----------
// double-buffered cp.async; EPI: 0 = +bias (fp32 out); 1 = +bias,GELU (bf16 out);
//                            2 = +bias +residual (fp32 out)
#define KC 32                 // bf16 K elements per chunk
#define SROW 20               // u32 words per smem row (16 data + 4 pad)
#define BUFW (128 * SROW)     // words per buffer
template <int EPI>
__global__ void __launch_bounds__(256, 2)
k_bgemm(const __nv_bfloat16* __restrict__ A, const __nv_bfloat16* __restrict__ BT,
        const float* __restrict__ bias, const float* __restrict__ res,
        void* __restrict__ Cout, int K, int N) {
    __shared__ __align__(16) uint32_t sA[2][BUFW];
    __shared__ __align__(16) uint32_t sB[2][BUFW];
    int tid = threadIdx.x;
    int wid = tid >> 5, lane = tid & 31;
    int wm = wid & 3, wn = wid >> 2;          // warp grid 4(M) x 2(N)
    int m0 = blockIdx.y << 7, n0 = blockIdx.x << 7;
    int g = lane >> 2, cq = lane & 3;

    float acc[2][8][4];
    #pragma unroll
    for (int i = 0; i < 2; i++)
        #pragma unroll
        for (int j = 0; j < 8; j++)
            #pragma unroll
            for (int q = 0; q < 4; q++) acc[i][j][q] = 0.0f;

    uint32_t sAu = smem_u32(sA), sBu = smem_u32(sB);
    int lrow = tid & 127;
    int lhalf = tid >> 7;                     // 0/1 -> bf16 col offset 0/16
    const __nv_bfloat16* Asrc0 = A  + (size_t)(m0 + lrow) * K + lhalf * 16;
    const __nv_bfloat16* Bsrc0 = BT + (size_t)(n0 + lrow) * K + lhalf * 16;
    uint32_t Adst0 = sAu + (lrow * SROW + lhalf * 8) * 4;
    uint32_t Bdst0 = sBu + (lrow * SROW + lhalf * 8) * 4;

    int nch = K >> 5;
    // prologue: chunk 0 -> buffer 0
    cpa16(Adst0,      Asrc0);     cpa16(Adst0 + 16, Asrc0 + 8);
    cpa16(Bdst0,      Bsrc0);     cpa16(Bdst0 + 16, Bsrc0 + 8);
    asm volatile("cp.async.commit_group;" ::: "memory");

    for (int ch = 0; ch < nch; ch++) {
        if (ch + 1 < nch) {
            int b = (ch + 1) & 1;
            const __nv_bfloat16* As = Asrc0 + (ch + 1) * KC;
            const __nv_bfloat16* Bs = Bsrc0 + (ch + 1) * KC;
            cpa16(Adst0 + b * BUFW * 4,      As);
            cpa16(Adst0 + b * BUFW * 4 + 16, As + 8);
            cpa16(Bdst0 + b * BUFW * 4,      Bs);
            cpa16(Bdst0 + b * BUFW * 4 + 16, Bs + 8);
            asm volatile("cp.async.commit_group;" ::: "memory");
            asm volatile("cp.async.wait_group 1;" ::: "memory");
        } else {
            asm volatile("cp.async.wait_group 0;" ::: "memory");
        }
        __syncthreads();
        int b = ch & 1;
        #pragma unroll
        for (int kk = 0; kk < 2; kk++) {      // two k=16 steps per chunk
            int kw = kk * 8;
            uint32_t a[2][4], bb[8][2];
            #pragma unroll
            for (int ma = 0; ma < 2; ma++) {
                int r = wm * 32 + ma * 16 + g;
                a[ma][0] = sA[b][r * SROW + kw + cq];
                a[ma][1] = sA[b][(r + 8) * SROW + kw + cq];
                a[ma][2] = sA[b][r * SROW + kw + cq + 4];
                a[ma][3] = sA[b][(r + 8) * SROW + kw + cq + 4];
            }
            #pragma unroll
            for (int na = 0; na < 8; na++) {
                int cl = wn * 64 + na * 8 + g;
                bb[na][0] = sB[b][cl * SROW + kw + cq];
                bb[na][1] = sB[b][cl * SROW + kw + cq + 4];
            }
            #pragma unroll
            for (int ma = 0; ma < 2; ma++)
                #pragma unroll
                for (int na = 0; na < 8; na++)
                    asm volatile(
                        "mma.sync.aligned.m16n8k16.row.col.f32.bf16.bf16.f32 "
                        "{%0,%1,%2,%3}, {%4,%5,%6,%7}, {%8,%9}, {%0,%1,%2,%3};"
                        : "+f"(acc[ma][na][0]), "+f"(acc[ma][na][1]),
                          "+f"(acc[ma][na][2]), "+f"(acc[ma][na][3])
                        : "r"(a[ma][0]), "r"(a[ma][1]), "r"(a[ma][2]), "r"(a[ma][3]),
                          "r"(bb[na][0]), "r"(bb[na][1]));
        }
        __syncthreads();
    }

    // epilogue
    #pragma unroll
    for (int ma = 0; ma < 2; ma++) {
        int r0 = m0 + wm * 32 + ma * 16 + g;
        #pragma unroll
        for (int na = 0; na < 8; na++) {
            int cb = n0 + wn * 64 + na * 8 + 2 * cq;
            float b0 = bias[cb], b1 = bias[cb + 1];
            float v0 = acc[ma][na][0] + b0;
            float v1 = acc[ma][na][1] + b1;
            float v2 = acc[ma][na][2] + b0;
            float v3 = acc[ma][na][3] + b1;
            if (EPI == 1) {
                v0 = 0.5f * v0 * (1.0f + erff(v0 * 0.7071067811865476f));
                v1 = 0.5f * v1 * (1.0f + erff(v1 * 0.7071067811865476f));
                v2 = 0.5f * v2 * (1.0f + erff(v2 * 0.7071067811865476f));
                v3 = 0.5f * v3 * (1.0f + erff(v3 * 0.7071067811865476f));
                __nv_bfloat16* Cb = (__nv_bfloat16*)Cout;
                *(__nv_bfloat162*)(Cb + (size_t)r0 * N + cb) =
                    __floats2bfloat162_rn(v0, v1);
                *(__nv_bfloat162*)(Cb + (size_t)(r0 + 8) * N + cb) =
                    __floats2bfloat162_rn(v2, v3);
            } else {
                if (EPI == 2) {
                    float2 r1v = *(const float2*)(res + (size_t)r0 * N + cb);
                    float2 r2v = *(const float2*)(res + (size_t)(r0 + 8) * N + cb);
                    v0 += r1v.x; v1 += r1v.y; v2 += r2v.x; v3 += r2v.y;
                }
                float* Cf = (float*)Cout;
                *(float2*)(Cf + (size_t)r0 * N + cb)       = make_float2(v0, v1);
                *(float2*)(Cf + (size_t)(r0 + 8) * N + cb) = make_float2(v2, v3);
            }
        }
    }
}

// ---------------- kernel 3: windowed attention per (window, head) ------------
__device__ __forceinline__ int region_of(int p) {
    return p < Himg - WS ? 0 : (p < Himg - SHIFT ? 1 : 2);
}

__global__ void k_attn(const float* __restrict__ qkv,
                       const float* __restrict__ rpb) {
    __shared__ float q[NTOK * QS], k[NTOK * QS], v[NTOK * QS], p[NTOK * NTOK];
    int w = blockIdx.x, h = blockIdx.y;
    int tid = threadIdx.x;
    for (int i = tid; i < NTOK * HD; i += 128) {
        int t = i / HD, d = i - t * HD;
        const float* base = qkv + (size_t)(w * NTOK + t) * (3 * DIM) + h * HD + d;
        q[t * QS + d] = base[0];
        k[t * QS + d] = base[DIM];
        v[t * QS + d] = base[2 * DIM];
    }
    __syncthreads();
    int wi = w & 63, wy = wi >> 3, wx = wi & 7;
    const float scale = 0.17677669529663687f;
    for (int i = tid; i < NTOK * NTOK; i += 128) {
        int n = i / NTOK, m = i - n * NTOK;
        float s = 0.0f;
        #pragma unroll
        for (int d = 0; d < HD; d++) s += q[n * QS + d] * k[m * QS + d];
        int iy = n / WS, ix = n - iy * WS;
        int jy = m / WS, jx = m - jy * WS;
        int rel = (iy - jy + WS - 1) * (2 * WS - 1) + (ix - jx + WS - 1);
        s = s * scale + rpb[rel * HEADS + h];
        int ln = region_of(wy * WS + iy) * 3 + region_of(wx * WS + ix);
        int lm = region_of(wy * WS + jy) * 3 + region_of(wx * WS + jx);
        if (ln != lm) s -= 100.0f;
        p[i] = s;
    }
    __syncthreads();
    if (tid < NTOK) {
        float mx = -1e30f;
        #pragma unroll 7
        for (int m = 0; m < NTOK; m++) mx = fmaxf(mx, p[tid * NTOK + m]);
        float sum = 0.0f;
        #pragma unroll 7
        for (int m = 0; m < NTOK; m++) {
            float e = __expf(p[tid * NTOK + m] - mx);
            p[tid * NTOK + m] = e;
            sum += e;
        }
        float inv = 1.0f / sum;
        #pragma unroll 7
        for (int m = 0; m < NTOK; m++) p[tid * NTOK + m] *= inv;
    }
    __syncthreads();
    for (int i = tid; i < NTOK * HD; i += 128) {
        int n = i / HD, d = i - n * HD;
        float s = 0.0f;
        #pragma unroll 7
        for (int m = 0; m < NTOK; m++) s += p[n * NTOK + m] * v[m * QS + d];
        g_attn[(size_t)(w * NTOK + n) * DIM + h * HD + d] = __float2bfloat16(s);
    }
}

// --------- kernel 5: window reverse + un-shift + residual + LN2 --------------
__global__ void k_rev_res_ln2(const float* __restrict__ x,
                              const float* __restrict__ gw,
                              const float* __restrict__ gb) {
    __shared__ float s1[4], s2[4];
    int t = blockIdx.x;
    int bimg = t / 3136, rc = t - bimg * 3136;
    int r = rc / 56, c = rc - r * 56;
    int rr = r - SHIFT; if (rr < 0) rr += Himg;
    int cc = c - SHIFT; if (cc < 0) cc += Wimg;
    int w = bimg * 64 + (rr / WS) * 8 + (cc / WS);
    int n = (rr % WS) * WS + (cc % WS);
    int ch = threadIdx.x;
    float v = x[(size_t)t * DIM + ch] + g_proj[(size_t)(w * NTOK + n) * DIM + ch];
    g_x2[(size_t)t * DIM + ch] = v;
    float sv = v, sq = v * v;
    #pragma unroll
    for (int o = 16; o > 0; o >>= 1) {
        sv += __shfl_down_sync(0xffffffffu, sv, o);
        sq += __shfl_down_sync(0xffffffffu, sq, o);
    }
    if ((ch & 31) == 0) { s1[ch >> 5] = sv; s2[ch >> 5] = sq; }
    __syncthreads();
    float mean = (s1[0] + s1[1] + s1[2] + s1[3]) * (1.0f / 128.0f);
    float var  = (s2[0] + s2[1] + s2[2] + s2[3]) * (1.0f / 128.0f) - mean * mean;
    float inv  = rsqrtf(var + 1e-5f);
    g_ln2[(size_t)t * DIM + ch] = __float2bfloat16((v - mean) * inv * gw[ch] + gb[ch]);
}

// ------------------------------- launcher ------------------------------------
extern "C" void kernel_launch(void* const* d_in, const int* in_sizes, int n_in,
                              void* d_out, int out_size) {
    const float* x      = (const float*)d_in[0];
    const float* qkv_w  = (const float*)d_in[1];
    const float* qkv_b  = (const float*)d_in[2];
    const float* proj_w = (const float*)d_in[3];
    const float* proj_b = (const float*)d_in[4];
    const float* rpb    = (const float*)d_in[5];
    const float* n1w    = (const float*)d_in[6];
    const float* n1b    = (const float*)d_in[7];
    const float* n2w    = (const float*)d_in[8];
    const float* n2b    = (const float*)d_in[9];
    const float* w1     = (const float*)d_in[10];
    const float* b1     = (const float*)d_in[11];
    const float* w2     = (const float*)d_in[12];
    const float* b2     = (const float*)d_in[13];
    float* out = (float*)d_out;

    __nv_bfloat16 *p_xw, *p_attn, *p_ln2, *p_h, *p_wtq, *p_wtp, *p_wt1, *p_wt2;
    float *p_qkv, *p_proj, *p_x2;
    cudaGetSymbolAddress((void**)&p_xw,   g_xw);
    cudaGetSymbolAddress((void**)&p_qkv,  g_qkv);
    cudaGetSymbolAddress((void**)&p_attn, g_attn);
    cudaGetSymbolAddress((void**)&p_proj, g_proj);
    cudaGetSymbolAddress((void**)&p_x2,   g_x2);
    cudaGetSymbolAddress((void**)&p_ln2,  g_ln2);
    cudaGetSymbolAddress((void**)&p_h,    g_h);
    cudaGetSymbolAddress((void**)&p_wtq,  g_wt_qkv);
    cudaGetSymbolAddress((void**)&p_wtp,  g_wt_proj);
    cudaGetSymbolAddress((void**)&p_wt1,  g_wt1);
    cudaGetSymbolAddress((void**)&p_wt2,  g_wt2);

    // 0) weight transposes ([K,N] fp32 -> [N,K] bf16)
    k_transpose<<<(128*384 + 255) / 256, 256>>>(qkv_w,  p_wtq, 128, 384);
    k_transpose<<<(128*128 + 255) / 256, 256>>>(proj_w, p_wtp, 128, 128);
    k_transpose<<<(128*512 + 255) / 256, 256>>>(w1,     p_wt1, 128, 512);
    k_transpose<<<(512*128 + 255) / 256, 256>>>(w2,     p_wt2, 512, 128);

    // 1) LN1 + shift + window partition
    k_ln_shift_part<<<MTOK, 128>>>(x, n1w, n1b);

    // 2) QKV GEMM: [200704,128] @ [128,384] + bias -> fp32
    k_bgemm<0><<<dim3(3, MTOK / 128), 256>>>(p_xw, p_wtq, qkv_b, nullptr, p_qkv, 128, 384);

    // 3) windowed attention -> bf16
    k_attn<<<dim3(NWIN, HEADS), 128>>>(p_qkv, rpb);

    // 4) proj GEMM: [200704,128] @ [128,128] + bias -> fp32
    k_bgemm<0><<<dim3(1, MTOK / 128), 256>>>(p_attn, p_wtp, proj_b, nullptr, p_proj, 128, 128);

    // 5) window reverse + un-shift + residual + LN2
    k_rev_res_ln2<<<MTOK, 128>>>(x, n2w, n2b);

    // 6) MLP1: [200704,128] @ [128,512] + bias, exact GELU -> bf16
    k_bgemm<1><<<dim3(4, MTOK / 128), 256>>>(p_ln2, p_wt1, b1, nullptr, p_h, 128, 512);

    // 7) MLP2: [200704,512] @ [512,128] + bias + residual -> d_out fp32
    k_bgemm<2><<<dim3(1, MTOK / 128), 256>>>(p_h, p_wt2, b2, p_x2, out, 512, 128);
}

// round 5
// speedup vs baseline: 3.5173x; 1.4182x over previous
#include <cuda_runtime.h>
#include <cuda_bf16.h>
#include <math.h>
#include <stdint.h>

#define Himg 56
#define Wimg 56
#define WS 7
#define SHIFT 3
#define HEADS 4
#define DIM 128
#define NTOK 49
#define NWIN 4096           // 64 imgs * 64 windows
#define MTOK 200704         // NWIN * NTOK
#define HD 32
#define QS2 36              // padded fp32 row stride in attention smem

// ---------------- scratch (static device globals; no allocation) -------------
__device__ __nv_bfloat16 g_xw  [(size_t)MTOK * DIM];       // LN1 out
__device__ __nv_bfloat16 g_qkv [(size_t)MTOK * 3 * DIM];   // qkv (bf16)
__device__ __nv_bfloat16 g_attn[(size_t)MTOK * DIM];       // attention out
__device__ float         g_x2  [(size_t)MTOK * DIM];       // residual 1 (image layout)
__device__ __nv_bfloat16 g_ln2 [(size_t)MTOK * DIM];       // LN2 out (image layout)
__device__ __nv_bfloat16 g_h   [(size_t)MTOK * 4 * DIM];   // MLP hidden
// transposed weights [N, K] in bf16
__device__ __nv_bfloat16 g_wt_qkv [384 * 128];
__device__ __nv_bfloat16 g_wt_proj[128 * 128];
__device__ __nv_bfloat16 g_wt1    [512 * 128];
__device__ __nv_bfloat16 g_wt2    [128 * 512];

__device__ __forceinline__ uint32_t smem_u32(const void* p) {
    uint32_t a;
    asm("{ .reg .u64 t; cvta.to.shared.u64 t, %1; cvt.u32.u64 %0, t; }" : "=r"(a) : "l"(p));
    return a;
}
__device__ __forceinline__ void cpa16(uint32_t dst, const void* src) {
    asm volatile("cp.async.cg.shared.global [%0], [%1], 16;" :: "r"(dst), "l"(src));
}
// window token index -> image token index (reverse shift + window reverse)
__device__ __forceinline__ int img_of(int wt) {
    int w = wt / NTOK, n = wt - w * NTOK;
    int bimg = w >> 6, wi = w & 63;
    int rr = (wi >> 3) * WS + n / WS;
    int cc = (wi & 7)  * WS + n % WS;
    int r = rr + SHIFT; if (r >= Himg) r -= Himg;
    int c = cc + SHIFT; if (c >= Wimg) c -= Wimg;
    return bimg * 3136 + r * 56 + c;
}

// ---------------- kernel 1: LN1 + cyclic shift + window partition ------------
__global__ void k_ln_shift_part(const float* __restrict__ x,
                                const float* __restrict__ gw,
                                const float* __restrict__ gb) {
    __shared__ float s1[4], s2[4];
    int t = blockIdx.x;
    int win = t / NTOK, n = t - win * NTOK;
    int bimg = win >> 6, wi = win & 63;
    int rr = (wi >> 3) * WS + n / WS;
    int cc = (wi & 7)  * WS + n % WS;
    int r = rr + SHIFT; if (r >= Himg) r -= Himg;
    int c = cc + SHIFT; if (c >= Wimg) c -= Wimg;
    int ch = threadIdx.x;
    float v = x[((size_t)bimg * 3136 + r * 56 + c) * DIM + ch];
    float sv = v, sq = v * v;
    #pragma unroll
    for (int o = 16; o > 0; o >>= 1) {
        sv += __shfl_down_sync(0xffffffffu, sv, o);
        sq += __shfl_down_sync(0xffffffffu, sq, o);
    }
    if ((ch & 31) == 0) { s1[ch >> 5] = sv; s2[ch >> 5] = sq; }
    __syncthreads();
    float mean = (s1[0] + s1[1] + s1[2] + s1[3]) * (1.0f / 128.0f);
    float var  = (s2[0] + s2[1] + s2[2] + s2[3]) * (1.0f / 128.0f) - mean * mean;
    float inv  = rsqrtf(var + 1e-5f);
    g_xw[(size_t)t * DIM + ch] = __float2bfloat16((v - mean) * inv * gw[ch] + gb[ch]);
}

// ---------------- weight transpose: W[K,N] fp32 -> WT[N,K] bf16 ---------------
__global__ void k_transpose(const float* __restrict__ W, __nv_bfloat16* __restrict__ WT,
                            int Kd, int Nd) {
    int i = blockIdx.x * 256 + threadIdx.x;
    if (i < Kd * Nd) {
        int k = i / Nd, n = i - k * Nd;
        WT[(size_t)n * Kd + k] = __float2bfloat16(W[i]);
    }
}

// -------- bf16 HMMA GEMM: C[M,N] = A[M,K] @ BT[N,K]^T, 128x128 tile ----------
// EPI: 0 = +bias (bf16 out); 1 = +bias, GELU (bf16 out);
//      2 = +bias +residual[image rows] (fp32 out);
//      3 = +bias +residual[x, scattered] + LN2 -> ln2 bf16 (Cout) + x2 fp32 (out2)
#define KC 32
#define SROW 20
#define BUFW (128 * SROW)
template <int EPI>
__global__ void __launch_bounds__(256, 2)
k_bgemm(const __nv_bfloat16* __restrict__ A, const __nv_bfloat16* __restrict__ BT,
        const float* __restrict__ bias, const float* __restrict__ res,
        void* __restrict__ Cout, int K, int N,
        const float* __restrict__ lnw, const float* __restrict__ lnb,
        float* __restrict__ out2) {
    __shared__ __align__(16) uint32_t sA[2][BUFW];
    __shared__ __align__(16) uint32_t sB[2][BUFW];
    __shared__ float redS[2][128], redQ[2][128];
    int tid = threadIdx.x;
    int wid = tid >> 5, lane = tid & 31;
    int wm = wid & 3, wn = wid >> 2;
    int m0 = blockIdx.y << 7, n0 = blockIdx.x << 7;
    int g = lane >> 2, cq = lane & 3;

    float acc[2][8][4];
    #pragma unroll
    for (int i = 0; i < 2; i++)
        #pragma unroll
        for (int j = 0; j < 8; j++)
            #pragma unroll
            for (int q = 0; q < 4; q++) acc[i][j][q] = 0.0f;

    uint32_t sAu = smem_u32(sA), sBu = smem_u32(sB);
    int lrow = tid & 127;
    int lhalf = tid >> 7;
    const __nv_bfloat16* Asrc0 = A  + (size_t)(m0 + lrow) * K + lhalf * 16;
    const __nv_bfloat16* Bsrc0 = BT + (size_t)(n0 + lrow) * K + lhalf * 16;
    uint32_t Adst0 = sAu + (lrow * SROW + lhalf * 8) * 4;
    uint32_t Bdst0 = sBu + (lrow * SROW + lhalf * 8) * 4;

    int nch = K >> 5;
    cpa16(Adst0,      Asrc0);     cpa16(Adst0 + 16, Asrc0 + 8);
    cpa16(Bdst0,      Bsrc0);     cpa16(Bdst0 + 16, Bsrc0 + 8);
    asm volatile("cp.async.commit_group;" ::: "memory");

    for (int ch = 0; ch < nch; ch++) {
        if (ch + 1 < nch) {
            int b = (ch + 1) & 1;
            const __nv_bfloat16* As = Asrc0 + (ch + 1) * KC;
            const __nv_bfloat16* Bs = Bsrc0 + (ch + 1) * KC;
            cpa16(Adst0 + b * BUFW * 4,      As);
            cpa16(Adst0 + b * BUFW * 4 + 16, As + 8);
            cpa16(Bdst0 + b * BUFW * 4,      Bs);
            cpa16(Bdst0 + b * BUFW * 4 + 16, Bs + 8);
            asm volatile("cp.async.commit_group;" ::: "memory");
            asm volatile("cp.async.wait_group 1;" ::: "memory");
        } else {
            asm volatile("cp.async.wait_group 0;" ::: "memory");
        }
        __syncthreads();
        int b = ch & 1;
        #pragma unroll
        for (int kk = 0; kk < 2; kk++) {
            int kw = kk * 8;
            uint32_t a[2][4], bb[8][2];
            #pragma unroll
            for (int ma = 0; ma < 2; ma++) {
                int r = wm * 32 + ma * 16 + g;
                a[ma][0] = sA[b][r * SROW + kw + cq];
                a[ma][1] = sA[b][(r + 8) * SROW + kw + cq];
                a[ma][2] = sA[b][r * SROW + kw + cq + 4];
                a[ma][3] = sA[b][(r + 8) * SROW + kw + cq + 4];
            }
            #pragma unroll
            for (int na = 0; na < 8; na++) {
                int cl = wn * 64 + na * 8 + g;
                bb[na][0] = sB[b][cl * SROW + kw + cq];
                bb[na][1] = sB[b][cl * SROW + kw + cq + 4];
            }
            #pragma unroll
            for (int ma = 0; ma < 2; ma++)
                #pragma unroll
                for (int na = 0; na < 8; na++)
                    asm volatile(
                        "mma.sync.aligned.m16n8k16.row.col.f32.bf16.bf16.f32 "
                        "{%0,%1,%2,%3}, {%4,%5,%6,%7}, {%8,%9}, {%0,%1,%2,%3};"
                        : "+f"(acc[ma][na][0]), "+f"(acc[ma][na][1]),
                          "+f"(acc[ma][na][2]), "+f"(acc[ma][na][3])
                        : "r"(a[ma][0]), "r"(a[ma][1]), "r"(a[ma][2]), "r"(a[ma][3]),
                          "r"(bb[na][0]), "r"(bb[na][1]));
        }
        __syncthreads();
    }

    if (EPI == 3) {
        // fused: +bias +residual(x scattered) -> x2 ; LN -> ln2
        int tok[2][2];
        #pragma unroll
        for (int ma = 0; ma < 2; ma++) {
            int rA = m0 + wm * 32 + ma * 16 + g;
            tok[ma][0] = img_of(rA);
            tok[ma][1] = img_of(rA + 8);
        }
        float sum[2][2] = {}, sq[2][2] = {};
        #pragma unroll
        for (int ma = 0; ma < 2; ma++)
            #pragma unroll
            for (int na = 0; na < 8; na++) {
                int cb = n0 + wn * 64 + na * 8 + 2 * cq;
                float b0 = bias[cb], b1 = bias[cb + 1];
                float2 rA2 = *(const float2*)(res + (size_t)tok[ma][0] * DIM + cb);
                float2 rB2 = *(const float2*)(res + (size_t)tok[ma][1] * DIM + cb);
                float v0 = acc[ma][na][0] + b0 + rA2.x;
                float v1 = acc[ma][na][1] + b1 + rA2.y;
                float v2 = acc[ma][na][2] + b0 + rB2.x;
                float v3 = acc[ma][na][3] + b1 + rB2.y;
                acc[ma][na][0] = v0; acc[ma][na][1] = v1;
                acc[ma][na][2] = v2; acc[ma][na][3] = v3;
                sum[ma][0] += v0 + v1;  sq[ma][0] += v0 * v0 + v1 * v1;
                sum[ma][1] += v2 + v3;  sq[ma][1] += v2 * v2 + v3 * v3;
            }
        #pragma unroll
        for (int ma = 0; ma < 2; ma++)
            #pragma unroll
            for (int rb = 0; rb < 2; rb++) {
                sum[ma][rb] += __shfl_xor_sync(0xffffffffu, sum[ma][rb], 1);
                sum[ma][rb] += __shfl_xor_sync(0xffffffffu, sum[ma][rb], 2);
                sq[ma][rb]  += __shfl_xor_sync(0xffffffffu, sq[ma][rb], 1);
                sq[ma][rb]  += __shfl_xor_sync(0xffffffffu, sq[ma][rb], 2);
            }
        if (cq == 0) {
            #pragma unroll
            for (int ma = 0; ma < 2; ma++)
                #pragma unroll
                for (int rb = 0; rb < 2; rb++) {
                    int rr = wm * 32 + ma * 16 + rb * 8 + g;
                    redS[wn][rr] = sum[ma][rb];
                    redQ[wn][rr] = sq[ma][rb];
                }
        }
        __syncthreads();
        float mean[2][2], inv[2][2];
        #pragma unroll
        for (int ma = 0; ma < 2; ma++)
            #pragma unroll
            for (int rb = 0; rb < 2; rb++) {
                int rr = wm * 32 + ma * 16 + rb * 8 + g;
                float ts = redS[0][rr] + redS[1][rr];
                float tq = redQ[0][rr] + redQ[1][rr];
                float mn = ts * (1.0f / 128.0f);
                float vr = tq * (1.0f / 128.0f) - mn * mn;
                mean[ma][rb] = mn;
                inv[ma][rb] = rsqrtf(vr + 1e-5f);
            }
        __nv_bfloat16* Cb = (__nv_bfloat16*)Cout;
        #pragma unroll
        for (int ma = 0; ma < 2; ma++)
            #pragma unroll
            for (int na = 0; na < 8; na++) {
                int cb = n0 + wn * 64 + na * 8 + 2 * cq;
                float w0 = lnw[cb], w1 = lnw[cb + 1];
                float e0 = lnb[cb], e1 = lnb[cb + 1];
                #pragma unroll
                for (int rb = 0; rb < 2; rb++) {
                    int ti = tok[ma][rb];
                    float v0 = acc[ma][na][2 * rb], v1 = acc[ma][na][2 * rb + 1];
                    *(float2*)(out2 + (size_t)ti * DIM + cb) = make_float2(v0, v1);
                    float l0 = (v0 - mean[ma][rb]) * inv[ma][rb] * w0 + e0;
                    float l1 = (v1 - mean[ma][rb]) * inv[ma][rb] * w1 + e1;
                    *(__nv_bfloat162*)(Cb + (size_t)ti * DIM + cb) =
                        __floats2bfloat162_rn(l0, l1);
                }
            }
        return;
    }

    #pragma unroll
    for (int ma = 0; ma < 2; ma++) {
        int r0 = m0 + wm * 32 + ma * 16 + g;
        #pragma unroll
        for (int na = 0; na < 8; na++) {
            int cb = n0 + wn * 64 + na * 8 + 2 * cq;
            float b0 = bias[cb], b1 = bias[cb + 1];
            float v0 = acc[ma][na][0] + b0;
            float v1 = acc[ma][na][1] + b1;
            float v2 = acc[ma][na][2] + b0;
            float v3 = acc[ma][na][3] + b1;
            if (EPI == 1) {
                v0 = 0.5f * v0 * (1.0f + erff(v0 * 0.7071067811865476f));
                v1 = 0.5f * v1 * (1.0f + erff(v1 * 0.7071067811865476f));
                v2 = 0.5f * v2 * (1.0f + erff(v2 * 0.7071067811865476f));
                v3 = 0.5f * v3 * (1.0f + erff(v3 * 0.7071067811865476f));
            }
            if (EPI == 0 || EPI == 1) {
                __nv_bfloat16* Cb = (__nv_bfloat16*)Cout;
                *(__nv_bfloat162*)(Cb + (size_t)r0 * N + cb) =
                    __floats2bfloat162_rn(v0, v1);
                *(__nv_bfloat162*)(Cb + (size_t)(r0 + 8) * N + cb) =
                    __floats2bfloat162_rn(v2, v3);
            } else {
                float2 r1v = *(const float2*)(res + (size_t)r0 * N + cb);
                float2 r2v = *(const float2*)(res + (size_t)(r0 + 8) * N + cb);
                v0 += r1v.x; v1 += r1v.y; v2 += r2v.x; v3 += r2v.y;
                float* Cf = (float*)Cout;
                *(float2*)(Cf + (size_t)r0 * N + cb)       = make_float2(v0, v1);
                *(float2*)(Cf + (size_t)(r0 + 8) * N + cb) = make_float2(v2, v3);
            }
        }
    }
}

// ---------------- kernel 3: windowed attention per (window, head) ------------
__device__ __forceinline__ int region_of(int p) {
    return p < Himg - WS ? 0 : (p < Himg - SHIFT ? 1 : 2);
}

__global__ void k_attn(const __nv_bfloat16* __restrict__ qkv,
                       const float* __restrict__ rpb) {
    __shared__ float q[64 * QS2], k[64 * QS2], v[64 * QS2], p[64 * NTOK];
    int w = blockIdx.x, h = blockIdx.y;
    int tid = threadIdx.x;                     // 128 threads
    for (int i = tid; i < NTOK * HD; i += 128) {
        int t = i >> 5, d = i & 31;
        const __nv_bfloat16* base = qkv + (size_t)(w * NTOK + t) * (3 * DIM) + h * HD + d;
        q[t * QS2 + d] = __bfloat162float(base[0]);
        k[t * QS2 + d] = __bfloat162float(base[DIM]);
        v[t * QS2 + d] = __bfloat162float(base[2 * DIM]);
    }
    // zero the pad rows 49..63 of q and k (read by the tiled loops)
    for (int i = tid; i < (64 - NTOK) * HD; i += 128) {
        int t = NTOK + (i >> 5), d = i & 31;
        q[t * QS2 + d] = 0.0f;
        k[t * QS2 + d] = 0.0f;
    }
    __syncthreads();

    int ty = tid >> 3, tx = tid & 7;           // 16 x 8 thread grid
    float acc[4][7];
    #pragma unroll
    for (int i = 0; i < 4; i++)
        #pragma unroll
        for (int j = 0; j < 7; j++) acc[i][j] = 0.0f;
    #pragma unroll
    for (int d = 0; d < HD; d++) {
        float a[4], b[7];
        #pragma unroll
        for (int i = 0; i < 4; i++) a[i] = q[(i * 16 + ty) * QS2 + d];
        #pragma unroll
        for (int j = 0; j < 7; j++) b[j] = k[(j * 8 + tx) * QS2 + d];
        #pragma unroll
        for (int i = 0; i < 4; i++)
            #pragma unroll
            for (int j = 0; j < 7; j++) acc[i][j] += a[i] * b[j];
    }

    int wi = w & 63, wy = wi >> 3, wx = wi & 7;
    const float scale = 0.17677669529663687f;
    #pragma unroll
    for (int i = 0; i < 4; i++) {
        int n = i * 16 + ty;
        if (n < NTOK) {
            int iy = n / WS, ix = n - iy * WS;
            int rn = region_of(wy * WS + iy) * 3 + region_of(wx * WS + ix);
            #pragma unroll
            for (int j = 0; j < 7; j++) {
                int m = j * 8 + tx;
                if (m < NTOK) {
                    int jy = m / WS, jx = m - jy * WS;
                    int rel = (iy - jy + WS - 1) * (2 * WS - 1) + (ix - jx + WS - 1);
                    float s = acc[i][j] * scale + rpb[rel * HEADS + h];
                    int rm = region_of(wy * WS + jy) * 3 + region_of(wx * WS + jx);
                    if (rn != rm) s -= 100.0f;
                    p[n * NTOK + m] = s;
                }
            }
        }
    }
    __syncthreads();
    if (tid < NTOK) {
        float mx = -1e30f;
        #pragma unroll 7
        for (int m = 0; m < NTOK; m++) mx = fmaxf(mx, p[tid * NTOK + m]);
        float sum = 0.0f;
        #pragma unroll 7
        for (int m = 0; m < NTOK; m++) {
            float e = __expf(p[tid * NTOK + m] - mx);
            p[tid * NTOK + m] = e;
            sum += e;
        }
        float inv = 1.0f / sum;
        #pragma unroll 7
        for (int m = 0; m < NTOK; m++) p[tid * NTOK + m] *= inv;
    }
    __syncthreads();

    float acc2[4][4];
    #pragma unroll
    for (int i = 0; i < 4; i++)
        #pragma unroll
        for (int l = 0; l < 4; l++) acc2[i][l] = 0.0f;
    #pragma unroll 7
    for (int m = 0; m < NTOK; m++) {
        float pv[4];
        #pragma unroll
        for (int i = 0; i < 4; i++) pv[i] = p[(i * 16 + ty) * NTOK + m];
        float4 vv = *(const float4*)&v[m * QS2 + tx * 4];
        #pragma unroll
        for (int i = 0; i < 4; i++) {
            acc2[i][0] += pv[i] * vv.x;
            acc2[i][1] += pv[i] * vv.y;
            acc2[i][2] += pv[i] * vv.z;
            acc2[i][3] += pv[i] * vv.w;
        }
    }
    #pragma unroll
    for (int i = 0; i < 4; i++) {
        int n = i * 16 + ty;
        if (n < NTOK) {
            __nv_bfloat162 o0 = __floats2bfloat162_rn(acc2[i][0], acc2[i][1]);
            __nv_bfloat162 o1 = __floats2bfloat162_rn(acc2[i][2], acc2[i][3]);
            uint2 pk;
            pk.x = *reinterpret_cast<uint32_t*>(&o0);
            pk.y = *reinterpret_cast<uint32_t*>(&o1);
            *(uint2*)(&g_attn[(size_t)(w * NTOK + n) * DIM + h * HD + tx * 4]) = pk;
        }
    }
}

// ------------------------------- launcher ------------------------------------
extern "C" void kernel_launch(void* const* d_in, const int* in_sizes, int n_in,
                              void* d_out, int out_size) {
    const float* x      = (const float*)d_in[0];
    const float* qkv_w  = (const float*)d_in[1];
    const float* qkv_b  = (const float*)d_in[2];
    const float* proj_w = (const float*)d_in[3];
    const float* proj_b = (const float*)d_in[4];
    const float* rpb    = (const float*)d_in[5];
    const float* n1w    = (const float*)d_in[6];
    const float* n1b    = (const float*)d_in[7];
    const float* n2w    = (const float*)d_in[8];
    const float* n2b    = (const float*)d_in[9];
    const float* w1     = (const float*)d_in[10];
    const float* b1     = (const float*)d_in[11];
    const float* w2     = (const float*)d_in[12];
    const float* b2     = (const float*)d_in[13];
    float* out = (float*)d_out;

    __nv_bfloat16 *p_xw, *p_qkv, *p_attn, *p_ln2, *p_h, *p_wtq, *p_wtp, *p_wt1, *p_wt2;
    float *p_x2;
    cudaGetSymbolAddress((void**)&p_xw,   g_xw);
    cudaGetSymbolAddress((void**)&p_qkv,  g_qkv);
    cudaGetSymbolAddress((void**)&p_attn, g_attn);
    cudaGetSymbolAddress((void**)&p_x2,   g_x2);
    cudaGetSymbolAddress((void**)&p_ln2,  g_ln2);
    cudaGetSymbolAddress((void**)&p_h,    g_h);
    cudaGetSymbolAddress((void**)&p_wtq,  g_wt_qkv);
    cudaGetSymbolAddress((void**)&p_wtp,  g_wt_proj);
    cudaGetSymbolAddress((void**)&p_wt1,  g_wt1);
    cudaGetSymbolAddress((void**)&p_wt2,  g_wt2);

    // 0) weight transposes ([K,N] fp32 -> [N,K] bf16)
    k_transpose<<<(128*384 + 255) / 256, 256>>>(qkv_w,  p_wtq, 128, 384);
    k_transpose<<<(128*128 + 255) / 256, 256>>>(proj_w, p_wtp, 128, 128);
    k_transpose<<<(128*512 + 255) / 256, 256>>>(w1,     p_wt1, 128, 512);
    k_transpose<<<(512*128 + 255) / 256, 256>>>(w2,     p_wt2, 512, 128);

    // 1) LN1 + shift + window partition
    k_ln_shift_part<<<MTOK, 128>>>(x, n1w, n1b);

    // 2) QKV GEMM -> bf16
    k_bgemm<0><<<dim3(3, MTOK / 128), 256>>>(p_xw, p_wtq, qkv_b, nullptr, p_qkv,
                                             128, 384, nullptr, nullptr, nullptr);

    // 3) windowed attention -> bf16
    k_attn<<<dim3(NWIN, HEADS), 128>>>(p_qkv, rpb);

    // 4) proj GEMM + residual + window-reverse + LN2 (fused)
    k_bgemm<3><<<dim3(1, MTOK / 128), 256>>>(p_attn, p_wtp, proj_b, x, p_ln2,
                                             128, 128, n2w, n2b, p_x2);

    // 5) MLP1 + GELU -> bf16
    k_bgemm<1><<<dim3(4, MTOK / 128), 256>>>(p_ln2, p_wt1, b1, nullptr, p_h,
                                             128, 512, nullptr, nullptr, nullptr);

    // 6) MLP2 + bias + residual -> d_out fp32
    k_bgemm<2><<<dim3(1, MTOK / 128), 256>>>(p_h, p_wt2, b2, p_x2, out,
                                             512, 128, nullptr, nullptr, nullptr);
}

// round 6
// speedup vs baseline: 3.5677x; 1.0143x over previous
#include <cuda_runtime.h>
#include <cuda_bf16.h>
#include <math.h>
#include <stdint.h>

#define Himg 56
#define Wimg 56
#define WS 7
#define SHIFT 3
#define HEADS 4
#define DIM 128
#define NTOK 49
#define NWIN 4096           // 64 imgs * 64 windows
#define MTOK 200704         // NWIN * NTOK
#define HD 32
#define QS2 36              // padded fp32 row stride in attention smem

// ---------------- scratch (static device globals; no allocation) -------------
__device__ __nv_bfloat16 g_xw  [(size_t)MTOK * DIM];
__device__ __nv_bfloat16 g_qkv [(size_t)MTOK * 3 * DIM];
__device__ __nv_bfloat16 g_attn[(size_t)MTOK * DIM];
__device__ float         g_x2  [(size_t)MTOK * DIM];
__device__ __nv_bfloat16 g_ln2 [(size_t)MTOK * DIM];
__device__ __nv_bfloat16 g_h   [(size_t)MTOK * 4 * DIM];
// transposed weights [N, K] in bf16
__device__ __nv_bfloat16 g_wt_qkv [384 * 128];
__device__ __nv_bfloat16 g_wt_proj[128 * 128];
__device__ __nv_bfloat16 g_wt1    [512 * 128];
__device__ __nv_bfloat16 g_wt2    [128 * 512];

__device__ __forceinline__ uint32_t smem_u32(const void* p) {
    uint32_t a;
    asm("{ .reg .u64 t; cvta.to.shared.u64 t, %1; cvt.u32.u64 %0, t; }" : "=r"(a) : "l"(p));
    return a;
}
__device__ __forceinline__ void cpa16(uint32_t dst, const void* src) {
    asm volatile("cp.async.cg.shared.global [%0], [%1], 16;" :: "r"(dst), "l"(src));
}
__device__ __forceinline__ int img_of(int wt) {
    int w = wt / NTOK, n = wt - w * NTOK;
    int bimg = w >> 6, wi = w & 63;
    int rr = (wi >> 3) * WS + n / WS;
    int cc = (wi & 7)  * WS + n % WS;
    int r = rr + SHIFT; if (r >= Himg) r -= Himg;
    int c = cc + SHIFT; if (c >= Wimg) c -= Wimg;
    return bimg * 3136 + r * 56 + c;
}

// ---------------- kernel 0: all 4 weight transposes fused ---------------------
__global__ void k_transpose_all(const float* __restrict__ qkv_w,
                                const float* __restrict__ proj_w,
                                const float* __restrict__ w1,
                                const float* __restrict__ w2) {
    int i = blockIdx.x * 256 + threadIdx.x;
    if (i < 49152) {                               // qkv: K=128, N=384
        int k = i / 384, n = i - k * 384;
        g_wt_qkv[n * 128 + k] = __float2bfloat16(qkv_w[i]);
    } else if (i < 65536) {                        // proj: 128x128
        int j = i - 49152;
        int k = j >> 7, n = j & 127;
        g_wt_proj[n * 128 + k] = __float2bfloat16(proj_w[j]);
    } else if (i < 131072) {                       // w1: K=128, N=512
        int j = i - 65536;
        int k = j >> 9, n = j & 511;
        g_wt1[n * 128 + k] = __float2bfloat16(w1[j]);
    } else if (i < 196608) {                       // w2: K=512, N=128
        int j = i - 131072;
        int k = j >> 7, n = j & 127;
        g_wt2[n * 512 + k] = __float2bfloat16(w2[j]);
    }
}

// ---------------- kernel 1: LN1 + cyclic shift + window partition ------------
__global__ void k_ln_shift_part(const float* __restrict__ x,
                                const float* __restrict__ gw,
                                const float* __restrict__ gb) {
    __shared__ float s1[4], s2[4];
    int t = blockIdx.x;
    int win = t / NTOK, n = t - win * NTOK;
    int bimg = win >> 6, wi = win & 63;
    int rr = (wi >> 3) * WS + n / WS;
    int cc = (wi & 7)  * WS + n % WS;
    int r = rr + SHIFT; if (r >= Himg) r -= Himg;
    int c = cc + SHIFT; if (c >= Wimg) c -= Wimg;
    int ch = threadIdx.x;
    float v = x[((size_t)bimg * 3136 + r * 56 + c) * DIM + ch];
    float sv = v, sq = v * v;
    #pragma unroll
    for (int o = 16; o > 0; o >>= 1) {
        sv += __shfl_down_sync(0xffffffffu, sv, o);
        sq += __shfl_down_sync(0xffffffffu, sq, o);
    }
    if ((ch & 31) == 0) { s1[ch >> 5] = sv; s2[ch >> 5] = sq; }
    __syncthreads();
    float mean = (s1[0] + s1[1] + s1[2] + s1[3]) * (1.0f / 128.0f);
    float var  = (s2[0] + s2[1] + s2[2] + s2[3]) * (1.0f / 128.0f) - mean * mean;
    float inv  = rsqrtf(var + 1e-5f);
    g_xw[(size_t)t * DIM + ch] = __float2bfloat16((v - mean) * inv * gw[ch] + gb[ch]);
}

// -------- bf16 HMMA GEMM with ldmatrix fragments, 128x128 tile ---------------
// EPI: 0 = +bias (bf16 out); 1 = +bias, GELU (bf16 out);
//      2 = +bias +residual (fp32 out);
//      3 = +bias +residual[x, scattered] + LN2 -> ln2 bf16 (Cout) + x2 fp32 (out2)
#define KC 32
#define SROW 20
#define BUFW (128 * SROW)
template <int EPI>
__global__ void __launch_bounds__(256, 2)
k_bgemm(const __nv_bfloat16* __restrict__ A, const __nv_bfloat16* __restrict__ BT,
        const float* __restrict__ bias, const float* __restrict__ res,
        void* __restrict__ Cout, int K, int N,
        const float* __restrict__ lnw, const float* __restrict__ lnb,
        float* __restrict__ out2) {
    __shared__ __align__(16) uint32_t sA[2][BUFW];
    __shared__ __align__(16) uint32_t sB[2][BUFW];
    __shared__ float redS[2][128], redQ[2][128];
    int tid = threadIdx.x;
    int wid = tid >> 5, lane = tid & 31;
    int wm = wid & 3, wn = wid >> 2;
    int m0 = blockIdx.y << 7, n0 = blockIdx.x << 7;
    int g = lane >> 2, cq = lane & 3;
    int mi = lane >> 3, l7 = lane & 7;

    float acc[2][8][4];
    #pragma unroll
    for (int i = 0; i < 2; i++)
        #pragma unroll
        for (int j = 0; j < 8; j++)
            #pragma unroll
            for (int q = 0; q < 4; q++) acc[i][j][q] = 0.0f;

    uint32_t sAu = smem_u32(sA), sBu = smem_u32(sB);
    int lrow = tid & 127;
    int lhalf = tid >> 7;
    const __nv_bfloat16* Asrc0 = A  + (size_t)(m0 + lrow) * K + lhalf * 16;
    const __nv_bfloat16* Bsrc0 = BT + (size_t)(n0 + lrow) * K + lhalf * 16;
    uint32_t Adst0 = sAu + (lrow * SROW + lhalf * 8) * 4;
    uint32_t Bdst0 = sBu + (lrow * SROW + lhalf * 8) * 4;

    // per-lane ldmatrix base offsets (within a buffer, kw/word-col added later)
    // A matrices: 0:(rows+0,k0) 1:(rows+8,k0) 2:(rows+0,k8) 3:(rows+8,k8)
    uint32_t aRow[2];
    #pragma unroll
    for (int ma = 0; ma < 2; ma++)
        aRow[ma] = (uint32_t)((wm * 32 + ma * 16 + ((mi & 1) << 3) + l7) * SROW +
                              ((mi >> 1) << 2)) * 4;
    // B matrices for pair np: 0:(tile 2np,k0) 1:(tile 2np,k8) 2:(tile 2np+1,k0) 3:(tile 2np+1,k8)
    uint32_t bRow[4];
    #pragma unroll
    for (int np = 0; np < 4; np++)
        bRow[np] = (uint32_t)((wn * 64 + np * 16 + ((mi >> 1) << 3) + l7) * SROW +
                              ((mi & 1) << 2)) * 4;

    int nch = K >> 5;
    cpa16(Adst0,      Asrc0);     cpa16(Adst0 + 16, Asrc0 + 8);
    cpa16(Bdst0,      Bsrc0);     cpa16(Bdst0 + 16, Bsrc0 + 8);
    asm volatile("cp.async.commit_group;" ::: "memory");

    for (int ch = 0; ch < nch; ch++) {
        if (ch + 1 < nch) {
            int b = (ch + 1) & 1;
            const __nv_bfloat16* As = Asrc0 + (ch + 1) * KC;
            const __nv_bfloat16* Bs = Bsrc0 + (ch + 1) * KC;
            cpa16(Adst0 + b * BUFW * 4,      As);
            cpa16(Adst0 + b * BUFW * 4 + 16, As + 8);
            cpa16(Bdst0 + b * BUFW * 4,      Bs);
            cpa16(Bdst0 + b * BUFW * 4 + 16, Bs + 8);
            asm volatile("cp.async.commit_group;" ::: "memory");
            asm volatile("cp.async.wait_group 1;" ::: "memory");
        } else {
            asm volatile("cp.async.wait_group 0;" ::: "memory");
        }
        __syncthreads();
        uint32_t baseA = sAu + (ch & 1) * BUFW * 4;
        uint32_t baseB = sBu + (ch & 1) * BUFW * 4;
        #pragma unroll
        for (int kk = 0; kk < 2; kk++) {
            uint32_t kwb = (uint32_t)(kk * 8) * 4;
            uint32_t a[2][4], bb[8][2];
            #pragma unroll
            for (int ma = 0; ma < 2; ma++)
                asm volatile(
                    "ldmatrix.sync.aligned.m8n8.x4.shared.b16 {%0,%1,%2,%3}, [%4];"
                    : "=r"(a[ma][0]), "=r"(a[ma][1]), "=r"(a[ma][2]), "=r"(a[ma][3])
                    : "r"(baseA + aRow[ma] + kwb));
            #pragma unroll
            for (int np = 0; np < 4; np++)
                asm volatile(
                    "ldmatrix.sync.aligned.m8n8.x4.shared.b16 {%0,%1,%2,%3}, [%4];"
                    : "=r"(bb[2*np][0]), "=r"(bb[2*np][1]),
                      "=r"(bb[2*np+1][0]), "=r"(bb[2*np+1][1])
                    : "r"(baseB + bRow[np] + kwb));
            #pragma unroll
            for (int ma = 0; ma < 2; ma++)
                #pragma unroll
                for (int na = 0; na < 8; na++)
                    asm volatile(
                        "mma.sync.aligned.m16n8k16.row.col.f32.bf16.bf16.f32 "
                        "{%0,%1,%2,%3}, {%4,%5,%6,%7}, {%8,%9}, {%0,%1,%2,%3};"
                        : "+f"(acc[ma][na][0]), "+f"(acc[ma][na][1]),
                          "+f"(acc[ma][na][2]), "+f"(acc[ma][na][3])
                        : "r"(a[ma][0]), "r"(a[ma][1]), "r"(a[ma][2]), "r"(a[ma][3]),
                          "r"(bb[na][0]), "r"(bb[na][1]));
        }
        __syncthreads();
    }

    if (EPI == 3) {
        int tok[2][2];
        #pragma unroll
        for (int ma = 0; ma < 2; ma++) {
            int rA = m0 + wm * 32 + ma * 16 + g;
            tok[ma][0] = img_of(rA);
            tok[ma][1] = img_of(rA + 8);
        }
        float sum[2][2] = {}, sq[2][2] = {};
        #pragma unroll
        for (int ma = 0; ma < 2; ma++)
            #pragma unroll
            for (int na = 0; na < 8; na++) {
                int cb = n0 + wn * 64 + na * 8 + 2 * cq;
                float b0 = bias[cb], b1 = bias[cb + 1];
                float2 rA2 = *(const float2*)(res + (size_t)tok[ma][0] * DIM + cb);
                float2 rB2 = *(const float2*)(res + (size_t)tok[ma][1] * DIM + cb);
                float v0 = acc[ma][na][0] + b0 + rA2.x;
                float v1 = acc[ma][na][1] + b1 + rA2.y;
                float v2 = acc[ma][na][2] + b0 + rB2.x;
                float v3 = acc[ma][na][3] + b1 + rB2.y;
                acc[ma][na][0] = v0; acc[ma][na][1] = v1;
                acc[ma][na][2] = v2; acc[ma][na][3] = v3;
                sum[ma][0] += v0 + v1;  sq[ma][0] += v0 * v0 + v1 * v1;
                sum[ma][1] += v2 + v3;  sq[ma][1] += v2 * v2 + v3 * v3;
            }
        #pragma unroll
        for (int ma = 0; ma < 2; ma++)
            #pragma unroll
            for (int rb = 0; rb < 2; rb++) {
                sum[ma][rb] += __shfl_xor_sync(0xffffffffu, sum[ma][rb], 1);
                sum[ma][rb] += __shfl_xor_sync(0xffffffffu, sum[ma][rb], 2);
                sq[ma][rb]  += __shfl_xor_sync(0xffffffffu, sq[ma][rb], 1);
                sq[ma][rb]  += __shfl_xor_sync(0xffffffffu, sq[ma][rb], 2);
            }
        if (cq == 0) {
            #pragma unroll
            for (int ma = 0; ma < 2; ma++)
                #pragma unroll
                for (int rb = 0; rb < 2; rb++) {
                    int rr = wm * 32 + ma * 16 + rb * 8 + g;
                    redS[wn][rr] = sum[ma][rb];
                    redQ[wn][rr] = sq[ma][rb];
                }
        }
        __syncthreads();
        float mean[2][2], inv[2][2];
        #pragma unroll
        for (int ma = 0; ma < 2; ma++)
            #pragma unroll
            for (int rb = 0; rb < 2; rb++) {
                int rr = wm * 32 + ma * 16 + rb * 8 + g;
                float ts = redS[0][rr] + redS[1][rr];
                float tq = redQ[0][rr] + redQ[1][rr];
                float mn = ts * (1.0f / 128.0f);
                float vr = tq * (1.0f / 128.0f) - mn * mn;
                mean[ma][rb] = mn;
                inv[ma][rb] = rsqrtf(vr + 1e-5f);
            }
        __nv_bfloat16* Cb = (__nv_bfloat16*)Cout;
        #pragma unroll
        for (int ma = 0; ma < 2; ma++)
            #pragma unroll
            for (int na = 0; na < 8; na++) {
                int cb = n0 + wn * 64 + na * 8 + 2 * cq;
                float w0 = lnw[cb], w1 = lnw[cb + 1];
                float e0 = lnb[cb], e1 = lnb[cb + 1];
                #pragma unroll
                for (int rb = 0; rb < 2; rb++) {
                    int ti = tok[ma][rb];
                    float v0 = acc[ma][na][2 * rb], v1 = acc[ma][na][2 * rb + 1];
                    *(float2*)(out2 + (size_t)ti * DIM + cb) = make_float2(v0, v1);
                    float l0 = (v0 - mean[ma][rb]) * inv[ma][rb] * w0 + e0;
                    float l1 = (v1 - mean[ma][rb]) * inv[ma][rb] * w1 + e1;
                    *(__nv_bfloat162*)(Cb + (size_t)ti * DIM + cb) =
                        __floats2bfloat162_rn(l0, l1);
                }
            }
        return;
    }

    #pragma unroll
    for (int ma = 0; ma < 2; ma++) {
        int r0 = m0 + wm * 32 + ma * 16 + g;
        #pragma unroll
        for (int na = 0; na < 8; na++) {
            int cb = n0 + wn * 64 + na * 8 + 2 * cq;
            float b0 = bias[cb], b1 = bias[cb + 1];
            float v0 = acc[ma][na][0] + b0;
            float v1 = acc[ma][na][1] + b1;
            float v2 = acc[ma][na][2] + b0;
            float v3 = acc[ma][na][3] + b1;
            if (EPI == 1) {
                v0 = 0.5f * v0 * (1.0f + erff(v0 * 0.7071067811865476f));
                v1 = 0.5f * v1 * (1.0f + erff(v1 * 0.7071067811865476f));
                v2 = 0.5f * v2 * (1.0f + erff(v2 * 0.7071067811865476f));
                v3 = 0.5f * v3 * (1.0f + erff(v3 * 0.7071067811865476f));
            }
            if (EPI == 0 || EPI == 1) {
                __nv_bfloat16* Cb = (__nv_bfloat16*)Cout;
                *(__nv_bfloat162*)(Cb + (size_t)r0 * N + cb) =
                    __floats2bfloat162_rn(v0, v1);
                *(__nv_bfloat162*)(Cb + (size_t)(r0 + 8) * N + cb) =
                    __floats2bfloat162_rn(v2, v3);
            } else {
                float2 r1v = *(const float2*)(res + (size_t)r0 * N + cb);
                float2 r2v = *(const float2*)(res + (size_t)(r0 + 8) * N + cb);
                v0 += r1v.x; v1 += r1v.y; v2 += r2v.x; v3 += r2v.y;
                float* Cf = (float*)Cout;
                *(float2*)(Cf + (size_t)r0 * N + cb)       = make_float2(v0, v1);
                *(float2*)(Cf + (size_t)(r0 + 8) * N + cb) = make_float2(v2, v3);
            }
        }
    }
}

// ---------------- kernel 3: windowed attention per (window, head) ------------
__device__ __forceinline__ int region_of(int p) {
    return p < Himg - WS ? 0 : (p < Himg - SHIFT ? 1 : 2);
}

__global__ void k_attn(const __nv_bfloat16* __restrict__ qkv,
                       const float* __restrict__ rpb) {
    __shared__ float q[64 * QS2], k[64 * QS2], v[64 * QS2], p[64 * NTOK];
    int w = blockIdx.x, h = blockIdx.y;
    int tid = threadIdx.x;
    for (int i = tid; i < NTOK * HD; i += 128) {
        int t = i >> 5, d = i & 31;
        const __nv_bfloat16* base = qkv + (size_t)(w * NTOK + t) * (3 * DIM) + h * HD + d;
        q[t * QS2 + d] = __bfloat162float(base[0]);
        k[t * QS2 + d] = __bfloat162float(base[DIM]);
        v[t * QS2 + d] = __bfloat162float(base[2 * DIM]);
    }
    for (int i = tid; i < (64 - NTOK) * HD; i += 128) {
        int t = NTOK + (i >> 5), d = i & 31;
        q[t * QS2 + d] = 0.0f;
        k[t * QS2 + d] = 0.0f;
    }
    __syncthreads();

    int ty = tid >> 3, tx = tid & 7;
    float acc[4][7];
    #pragma unroll
    for (int i = 0; i < 4; i++)
        #pragma unroll
        for (int j = 0; j < 7; j++) acc[i][j] = 0.0f;
    #pragma unroll
    for (int d = 0; d < HD; d++) {
        float a[4], b[7];
        #pragma unroll
        for (int i = 0; i < 4; i++) a[i] = q[(i * 16 + ty) * QS2 + d];
        #pragma unroll
        for (int j = 0; j < 7; j++) b[j] = k[(j * 8 + tx) * QS2 + d];
        #pragma unroll
        for (int i = 0; i < 4; i++)
            #pragma unroll
            for (int j = 0; j < 7; j++) acc[i][j] += a[i] * b[j];
    }

    int wi = w & 63, wy = wi >> 3, wx = wi & 7;
    const float scale = 0.17677669529663687f;
    #pragma unroll
    for (int i = 0; i < 4; i++) {
        int n = i * 16 + ty;
        if (n < NTOK) {
            int iy = n / WS, ix = n - iy * WS;
            int rn = region_of(wy * WS + iy) * 3 + region_of(wx * WS + ix);
            #pragma unroll
            for (int j = 0; j < 7; j++) {
                int m = j * 8 + tx;
                if (m < NTOK) {
                    int jy = m / WS, jx = m - jy * WS;
                    int rel = (iy - jy + WS - 1) * (2 * WS - 1) + (ix - jx + WS - 1);
                    float s = acc[i][j] * scale + rpb[rel * HEADS + h];
                    int rm = region_of(wy * WS + jy) * 3 + region_of(wx * WS + jx);
                    if (rn != rm) s -= 100.0f;
                    p[n * NTOK + m] = s;
                }
            }
        }
    }
    __syncthreads();
    if (tid < NTOK) {
        float mx = -1e30f;
        #pragma unroll 7
        for (int m = 0; m < NTOK; m++) mx = fmaxf(mx, p[tid * NTOK + m]);
        float sum = 0.0f;
        #pragma unroll 7
        for (int m = 0; m < NTOK; m++) {
            float e = __expf(p[tid * NTOK + m] - mx);
            p[tid * NTOK + m] = e;
            sum += e;
        }
        float inv = 1.0f / sum;
        #pragma unroll 7
        for (int m = 0; m < NTOK; m++) p[tid * NTOK + m] *= inv;
    }
    __syncthreads();

    float acc2[4][4];
    #pragma unroll
    for (int i = 0; i < 4; i++)
        #pragma unroll
        for (int l = 0; l < 4; l++) acc2[i][l] = 0.0f;
    #pragma unroll 7
    for (int m = 0; m < NTOK; m++) {
        float pv[4];
        #pragma unroll
        for (int i = 0; i < 4; i++) pv[i] = p[(i * 16 + ty) * NTOK + m];
        float4 vv = *(const float4*)&v[m * QS2 + tx * 4];
        #pragma unroll
        for (int i = 0; i < 4; i++) {
            acc2[i][0] += pv[i] * vv.x;
            acc2[i][1] += pv[i] * vv.y;
            acc2[i][2] += pv[i] * vv.z;
            acc2[i][3] += pv[i] * vv.w;
        }
    }
    #pragma unroll
    for (int i = 0; i < 4; i++) {
        int n = i * 16 + ty;
        if (n < NTOK) {
            __nv_bfloat162 o0 = __floats2bfloat162_rn(acc2[i][0], acc2[i][1]);
            __nv_bfloat162 o1 = __floats2bfloat162_rn(acc2[i][2], acc2[i][3]);
            uint2 pk;
            pk.x = *reinterpret_cast<uint32_t*>(&o0);
            pk.y = *reinterpret_cast<uint32_t*>(&o1);
            *(uint2*)(&g_attn[(size_t)(w * NTOK + n) * DIM + h * HD + tx * 4]) = pk;
        }
    }
}

// ------------------------------- launcher ------------------------------------
extern "C" void kernel_launch(void* const* d_in, const int* in_sizes, int n_in,
                              void* d_out, int out_size) {
    const float* x      = (const float*)d_in[0];
    const float* qkv_w  = (const float*)d_in[1];
    const float* qkv_b  = (const float*)d_in[2];
    const float* proj_w = (const float*)d_in[3];
    const float* proj_b = (const float*)d_in[4];
    const float* rpb    = (const float*)d_in[5];
    const float* n1w    = (const float*)d_in[6];
    const float* n1b    = (const float*)d_in[7];
    const float* n2w    = (const float*)d_in[8];
    const float* n2b    = (const float*)d_in[9];
    const float* w1     = (const float*)d_in[10];
    const float* b1     = (const float*)d_in[11];
    const float* w2     = (const float*)d_in[12];
    const float* b2     = (const float*)d_in[13];
    float* out = (float*)d_out;

    __nv_bfloat16 *p_xw, *p_qkv, *p_attn, *p_ln2, *p_h, *p_wtq, *p_wtp, *p_wt1, *p_wt2;
    float *p_x2;
    cudaGetSymbolAddress((void**)&p_xw,   g_xw);
    cudaGetSymbolAddress((void**)&p_qkv,  g_qkv);
    cudaGetSymbolAddress((void**)&p_attn, g_attn);
    cudaGetSymbolAddress((void**)&p_x2,   g_x2);
    cudaGetSymbolAddress((void**)&p_ln2,  g_ln2);
    cudaGetSymbolAddress((void**)&p_h,    g_h);
    cudaGetSymbolAddress((void**)&p_wtq,  g_wt_qkv);
    cudaGetSymbolAddress((void**)&p_wtp,  g_wt_proj);
    cudaGetSymbolAddress((void**)&p_wt1,  g_wt1);
    cudaGetSymbolAddress((void**)&p_wt2,  g_wt2);

    // 0) fused weight transposes
    k_transpose_all<<<768, 256>>>(qkv_w, proj_w, w1, w2);

    // 1) LN1 + shift + window partition
    k_ln_shift_part<<<MTOK, 128>>>(x, n1w, n1b);

    // 2) QKV GEMM -> bf16
    k_bgemm<0><<<dim3(3, MTOK / 128), 256>>>(p_xw, p_wtq, qkv_b, nullptr, p_qkv,
                                             128, 384, nullptr, nullptr, nullptr);

    // 3) windowed attention -> bf16
    k_attn<<<dim3(NWIN, HEADS), 128>>>(p_qkv, rpb);

    // 4) proj GEMM + residual + window-reverse + LN2 (fused)
    k_bgemm<3><<<dim3(1, MTOK / 128), 256>>>(p_attn, p_wtp, proj_b, x, p_ln2,
                                             128, 128, n2w, n2b, p_x2);

    // 5) MLP1 + GELU -> bf16
    k_bgemm<1><<<dim3(4, MTOK / 128), 256>>>(p_ln2, p_wt1, b1, nullptr, p_h,
                                             128, 512, nullptr, nullptr, nullptr);

    // 6) MLP2 + bias + residual -> d_out fp32
    k_bgemm<2><<<dim3(1, MTOK / 128), 256>>>(p_h, p_wt2, b2, p_x2, out,
                                             512, 128, nullptr, nullptr, nullptr);
}

// round 7
// speedup vs baseline: 4.4365x; 1.2435x over previous
#include <cuda_runtime.h>
#include <cuda_bf16.h>
#include <math.h>
#include <stdint.h>

#define Himg 56
#define Wimg 56
#define WS 7
#define SHIFT 3
#define HEADS 4
#define DIM 128
#define NTOK 49
#define NWIN 4096           // 64 imgs * 64 windows
#define MTOK 200704         // NWIN * NTOK
#define HD 32

// ---------------- scratch (static device globals; no allocation) -------------
__device__ __nv_bfloat16 g_xw  [(size_t)MTOK * DIM];
__device__ __nv_bfloat16 g_qkv [(size_t)MTOK * 3 * DIM];
__device__ __nv_bfloat16 g_attn[(size_t)MTOK * DIM];
__device__ float         g_x2  [(size_t)MTOK * DIM];
__device__ __nv_bfloat16 g_ln2 [(size_t)MTOK * DIM];
__device__ __nv_bfloat16 g_h   [(size_t)MTOK * 4 * DIM];
// transposed weights [N, K] in bf16
__device__ __nv_bfloat16 g_wt_qkv [384 * 128];
__device__ __nv_bfloat16 g_wt_proj[128 * 128];
__device__ __nv_bfloat16 g_wt1    [512 * 128];
__device__ __nv_bfloat16 g_wt2    [128 * 512];

__device__ __forceinline__ uint32_t smem_u32(const void* p) {
    uint32_t a;
    asm("{ .reg .u64 t; cvta.to.shared.u64 t, %1; cvt.u32.u64 %0, t; }" : "=r"(a) : "l"(p));
    return a;
}
__device__ __forceinline__ void cpa16(uint32_t dst, const void* src) {
    asm volatile("cp.async.cg.shared.global [%0], [%1], 16;" :: "r"(dst), "l"(src));
}
__device__ __forceinline__ int img_of(int wt) {
    int w = wt / NTOK, n = wt - w * NTOK;
    int bimg = w >> 6, wi = w & 63;
    int rr = (wi >> 3) * WS + n / WS;
    int cc = (wi & 7)  * WS + n % WS;
    int r = rr + SHIFT; if (r >= Himg) r -= Himg;
    int c = cc + SHIFT; if (c >= Wimg) c -= Wimg;
    return bimg * 3136 + r * 56 + c;
}

// ---------------- kernel 0: all 4 weight transposes fused ---------------------
__global__ void k_transpose_all(const float* __restrict__ qkv_w,
                                const float* __restrict__ proj_w,
                                const float* __restrict__ w1,
                                const float* __restrict__ w2) {
    int i = blockIdx.x * 256 + threadIdx.x;
    if (i < 49152) {
        int k = i / 384, n = i - k * 384;
        g_wt_qkv[n * 128 + k] = __float2bfloat16(qkv_w[i]);
    } else if (i < 65536) {
        int j = i - 49152;
        int k = j >> 7, n = j & 127;
        g_wt_proj[n * 128 + k] = __float2bfloat16(proj_w[j]);
    } else if (i < 131072) {
        int j = i - 65536;
        int k = j >> 9, n = j & 511;
        g_wt1[n * 128 + k] = __float2bfloat16(w1[j]);
    } else if (i < 196608) {
        int j = i - 131072;
        int k = j >> 7, n = j & 127;
        g_wt2[n * 512 + k] = __float2bfloat16(w2[j]);
    }
}

// ---------------- kernel 1: LN1 + cyclic shift + window partition ------------
__global__ void k_ln_shift_part(const float* __restrict__ x,
                                const float* __restrict__ gw,
                                const float* __restrict__ gb) {
    __shared__ float s1[4], s2[4];
    int t = blockIdx.x;
    int win = t / NTOK, n = t - win * NTOK;
    int bimg = win >> 6, wi = win & 63;
    int rr = (wi >> 3) * WS + n / WS;
    int cc = (wi & 7)  * WS + n % WS;
    int r = rr + SHIFT; if (r >= Himg) r -= Himg;
    int c = cc + SHIFT; if (c >= Wimg) c -= Wimg;
    int ch = threadIdx.x;
    float v = x[((size_t)bimg * 3136 + r * 56 + c) * DIM + ch];
    float sv = v, sq = v * v;
    #pragma unroll
    for (int o = 16; o > 0; o >>= 1) {
        sv += __shfl_down_sync(0xffffffffu, sv, o);
        sq += __shfl_down_sync(0xffffffffu, sq, o);
    }
    if ((ch & 31) == 0) { s1[ch >> 5] = sv; s2[ch >> 5] = sq; }
    __syncthreads();
    float mean = (s1[0] + s1[1] + s1[2] + s1[3]) * (1.0f / 128.0f);
    float var  = (s2[0] + s2[1] + s2[2] + s2[3]) * (1.0f / 128.0f) - mean * mean;
    float inv  = rsqrtf(var + 1e-5f);
    g_xw[(size_t)t * DIM + ch] = __float2bfloat16((v - mean) * inv * gw[ch] + gb[ch]);
}

// -------- bf16 HMMA GEMM with ldmatrix fragments, 128x128 tile ---------------
#define KC 32
#define SROW 20
#define BUFW (128 * SROW)
template <int EPI>
__global__ void __launch_bounds__(256, 2)
k_bgemm(const __nv_bfloat16* __restrict__ A, const __nv_bfloat16* __restrict__ BT,
        const float* __restrict__ bias, const float* __restrict__ res,
        void* __restrict__ Cout, int K, int N,
        const float* __restrict__ lnw, const float* __restrict__ lnb,
        float* __restrict__ out2) {
    __shared__ __align__(16) uint32_t sA[2][BUFW];
    __shared__ __align__(16) uint32_t sB[2][BUFW];
    __shared__ float redS[2][128], redQ[2][128];
    int tid = threadIdx.x;
    int wid = tid >> 5, lane = tid & 31;
    int wm = wid & 3, wn = wid >> 2;
    int m0 = blockIdx.y << 7, n0 = blockIdx.x << 7;
    int g = lane >> 2, cq = lane & 3;
    int mi = lane >> 3, l7 = lane & 7;

    float acc[2][8][4];
    #pragma unroll
    for (int i = 0; i < 2; i++)
        #pragma unroll
        for (int j = 0; j < 8; j++)
            #pragma unroll
            for (int q = 0; q < 4; q++) acc[i][j][q] = 0.0f;

    uint32_t sAu = smem_u32(sA), sBu = smem_u32(sB);
    int lrow = tid & 127;
    int lhalf = tid >> 7;
    const __nv_bfloat16* Asrc0 = A  + (size_t)(m0 + lrow) * K + lhalf * 16;
    const __nv_bfloat16* Bsrc0 = BT + (size_t)(n0 + lrow) * K + lhalf * 16;
    uint32_t Adst0 = sAu + (lrow * SROW + lhalf * 8) * 4;
    uint32_t Bdst0 = sBu + (lrow * SROW + lhalf * 8) * 4;

    uint32_t aRow[2];
    #pragma unroll
    for (int ma = 0; ma < 2; ma++)
        aRow[ma] = (uint32_t)((wm * 32 + ma * 16 + ((mi & 1) << 3) + l7) * SROW +
                              ((mi >> 1) << 2)) * 4;
    uint32_t bRow[4];
    #pragma unroll
    for (int np = 0; np < 4; np++)
        bRow[np] = (uint32_t)((wn * 64 + np * 16 + ((mi >> 1) << 3) + l7) * SROW +
                              ((mi & 1) << 2)) * 4;

    int nch = K >> 5;
    cpa16(Adst0,      Asrc0);     cpa16(Adst0 + 16, Asrc0 + 8);
    cpa16(Bdst0,      Bsrc0);     cpa16(Bdst0 + 16, Bsrc0 + 8);
    asm volatile("cp.async.commit_group;" ::: "memory");

    for (int ch = 0; ch < nch; ch++) {
        if (ch + 1 < nch) {
            int b = (ch + 1) & 1;
            const __nv_bfloat16* As = Asrc0 + (ch + 1) * KC;
            const __nv_bfloat16* Bs = Bsrc0 + (ch + 1) * KC;
            cpa16(Adst0 + b * BUFW * 4,      As);
            cpa16(Adst0 + b * BUFW * 4 + 16, As + 8);
            cpa16(Bdst0 + b * BUFW * 4,      Bs);
            cpa16(Bdst0 + b * BUFW * 4 + 16, Bs + 8);
            asm volatile("cp.async.commit_group;" ::: "memory");
            asm volatile("cp.async.wait_group 1;" ::: "memory");
        } else {
            asm volatile("cp.async.wait_group 0;" ::: "memory");
        }
        __syncthreads();
        uint32_t baseA = sAu + (ch & 1) * BUFW * 4;
        uint32_t baseB = sBu + (ch & 1) * BUFW * 4;
        #pragma unroll
        for (int kk = 0; kk < 2; kk++) {
            uint32_t kwb = (uint32_t)(kk * 8) * 4;
            uint32_t a[2][4], bb[8][2];
            #pragma unroll
            for (int ma = 0; ma < 2; ma++)
                asm volatile(
                    "ldmatrix.sync.aligned.m8n8.x4.shared.b16 {%0,%1,%2,%3}, [%4];"
                    : "=r"(a[ma][0]), "=r"(a[ma][1]), "=r"(a[ma][2]), "=r"(a[ma][3])
                    : "r"(baseA + aRow[ma] + kwb));
            #pragma unroll
            for (int np = 0; np < 4; np++)
                asm volatile(
                    "ldmatrix.sync.aligned.m8n8.x4.shared.b16 {%0,%1,%2,%3}, [%4];"
                    : "=r"(bb[2*np][0]), "=r"(bb[2*np][1]),
                      "=r"(bb[2*np+1][0]), "=r"(bb[2*np+1][1])
                    : "r"(baseB + bRow[np] + kwb));
            #pragma unroll
            for (int ma = 0; ma < 2; ma++)
                #pragma unroll
                for (int na = 0; na < 8; na++)
                    asm volatile(
                        "mma.sync.aligned.m16n8k16.row.col.f32.bf16.bf16.f32 "
                        "{%0,%1,%2,%3}, {%4,%5,%6,%7}, {%8,%9}, {%0,%1,%2,%3};"
                        : "+f"(acc[ma][na][0]), "+f"(acc[ma][na][1]),
                          "+f"(acc[ma][na][2]), "+f"(acc[ma][na][3])
                        : "r"(a[ma][0]), "r"(a[ma][1]), "r"(a[ma][2]), "r"(a[ma][3]),
                          "r"(bb[na][0]), "r"(bb[na][1]));
        }
        __syncthreads();
    }

    if (EPI == 3) {
        int tok[2][2];
        #pragma unroll
        for (int ma = 0; ma < 2; ma++) {
            int rA = m0 + wm * 32 + ma * 16 + g;
            tok[ma][0] = img_of(rA);
            tok[ma][1] = img_of(rA + 8);
        }
        float sum[2][2] = {}, sq[2][2] = {};
        #pragma unroll
        for (int ma = 0; ma < 2; ma++)
            #pragma unroll
            for (int na = 0; na < 8; na++) {
                int cb = n0 + wn * 64 + na * 8 + 2 * cq;
                float b0 = bias[cb], b1 = bias[cb + 1];
                float2 rA2 = *(const float2*)(res + (size_t)tok[ma][0] * DIM + cb);
                float2 rB2 = *(const float2*)(res + (size_t)tok[ma][1] * DIM + cb);
                float v0 = acc[ma][na][0] + b0 + rA2.x;
                float v1 = acc[ma][na][1] + b1 + rA2.y;
                float v2 = acc[ma][na][2] + b0 + rB2.x;
                float v3 = acc[ma][na][3] + b1 + rB2.y;
                acc[ma][na][0] = v0; acc[ma][na][1] = v1;
                acc[ma][na][2] = v2; acc[ma][na][3] = v3;
                sum[ma][0] += v0 + v1;  sq[ma][0] += v0 * v0 + v1 * v1;
                sum[ma][1] += v2 + v3;  sq[ma][1] += v2 * v2 + v3 * v3;
            }
        #pragma unroll
        for (int ma = 0; ma < 2; ma++)
            #pragma unroll
            for (int rb = 0; rb < 2; rb++) {
                sum[ma][rb] += __shfl_xor_sync(0xffffffffu, sum[ma][rb], 1);
                sum[ma][rb] += __shfl_xor_sync(0xffffffffu, sum[ma][rb], 2);
                sq[ma][rb]  += __shfl_xor_sync(0xffffffffu, sq[ma][rb], 1);
                sq[ma][rb]  += __shfl_xor_sync(0xffffffffu, sq[ma][rb], 2);
            }
        if (cq == 0) {
            #pragma unroll
            for (int ma = 0; ma < 2; ma++)
                #pragma unroll
                for (int rb = 0; rb < 2; rb++) {
                    int rr = wm * 32 + ma * 16 + rb * 8 + g;
                    redS[wn][rr] = sum[ma][rb];
                    redQ[wn][rr] = sq[ma][rb];
                }
        }
        __syncthreads();
        float mean[2][2], inv[2][2];
        #pragma unroll
        for (int ma = 0; ma < 2; ma++)
            #pragma unroll
            for (int rb = 0; rb < 2; rb++) {
                int rr = wm * 32 + ma * 16 + rb * 8 + g;
                float ts = redS[0][rr] + redS[1][rr];
                float tq = redQ[0][rr] + redQ[1][rr];
                float mn = ts * (1.0f / 128.0f);
                float vr = tq * (1.0f / 128.0f) - mn * mn;
                mean[ma][rb] = mn;
                inv[ma][rb] = rsqrtf(vr + 1e-5f);
            }
        __nv_bfloat16* Cb = (__nv_bfloat16*)Cout;
        #pragma unroll
        for (int ma = 0; ma < 2; ma++)
            #pragma unroll
            for (int na = 0; na < 8; na++) {
                int cb = n0 + wn * 64 + na * 8 + 2 * cq;
                float w0 = lnw[cb], w1 = lnw[cb + 1];
                float e0 = lnb[cb], e1 = lnb[cb + 1];
                #pragma unroll
                for (int rb = 0; rb < 2; rb++) {
                    int ti = tok[ma][rb];
                    float v0 = acc[ma][na][2 * rb], v1 = acc[ma][na][2 * rb + 1];
                    *(float2*)(out2 + (size_t)ti * DIM + cb) = make_float2(v0, v1);
                    float l0 = (v0 - mean[ma][rb]) * inv[ma][rb] * w0 + e0;
                    float l1 = (v1 - mean[ma][rb]) * inv[ma][rb] * w1 + e1;
                    *(__nv_bfloat162*)(Cb + (size_t)ti * DIM + cb) =
                        __floats2bfloat162_rn(l0, l1);
                }
            }
        return;
    }

    #pragma unroll
    for (int ma = 0; ma < 2; ma++) {
        int r0 = m0 + wm * 32 + ma * 16 + g;
        #pragma unroll
        for (int na = 0; na < 8; na++) {
            int cb = n0 + wn * 64 + na * 8 + 2 * cq;
            float b0 = bias[cb], b1 = bias[cb + 1];
            float v0 = acc[ma][na][0] + b0;
            float v1 = acc[ma][na][1] + b1;
            float v2 = acc[ma][na][2] + b0;
            float v3 = acc[ma][na][3] + b1;
            if (EPI == 1) {
                v0 = 0.5f * v0 * (1.0f + erff(v0 * 0.7071067811865476f));
                v1 = 0.5f * v1 * (1.0f + erff(v1 * 0.7071067811865476f));
                v2 = 0.5f * v2 * (1.0f + erff(v2 * 0.7071067811865476f));
                v3 = 0.5f * v3 * (1.0f + erff(v3 * 0.7071067811865476f));
            }
            if (EPI == 0 || EPI == 1) {
                __nv_bfloat16* Cb = (__nv_bfloat16*)Cout;
                *(__nv_bfloat162*)(Cb + (size_t)r0 * N + cb) =
                    __floats2bfloat162_rn(v0, v1);
                *(__nv_bfloat162*)(Cb + (size_t)(r0 + 8) * N + cb) =
                    __floats2bfloat162_rn(v2, v3);
            } else {
                float2 r1v = *(const float2*)(res + (size_t)r0 * N + cb);
                float2 r2v = *(const float2*)(res + (size_t)(r0 + 8) * N + cb);
                v0 += r1v.x; v1 += r1v.y; v2 += r2v.x; v3 += r2v.y;
                float* Cf = (float*)Cout;
                *(float2*)(Cf + (size_t)r0 * N + cb)       = make_float2(v0, v1);
                *(float2*)(Cf + (size_t)(r0 + 8) * N + cb) = make_float2(v2, v3);
            }
        }
    }
}

// ---------------- kernel 3: tensor-core windowed attention -------------------
__device__ __forceinline__ int region_of(int p) {
    return p < Himg - WS ? 0 : (p < Himg - SHIFT ? 1 : 2);
}
#define AS 40   // bf16 row stride (= 20 words, conflict-free, 16B-aligned rows)

__global__ void __launch_bounds__(128)
k_attn(const __nv_bfloat16* __restrict__ qkv, const float* __restrict__ rpb) {
    __shared__ __align__(16) __nv_bfloat16 sq[64 * AS], sk[64 * AS], sv[64 * AS];
    __shared__ float sb[169];
    int w = blockIdx.x, h = blockIdx.y;
    int tid = threadIdx.x, wq = tid >> 5, lane = tid & 31;
    int g = lane >> 2, cq = lane & 3;
    int mi = lane >> 3, l7 = lane & 7;

    // cooperative load: q/k/v rows 0..48 (uint4 = 8 bf16)
    for (int i = tid; i < NTOK * 12; i += 128) {
        int t = i / 12, rem = i - t * 12, z = rem >> 2, seg = rem & 3;
        const uint4* src = (const uint4*)(qkv + (size_t)(w * NTOK + t) * 384 +
                                          z * 128 + h * 32 + seg * 8);
        __nv_bfloat16* dst = (z == 0 ? sq : z == 1 ? sk : sv) + t * AS + seg * 8;
        *(uint4*)dst = *src;
    }
    // zero pad rows 49..63
    for (int i = tid; i < 15 * 12; i += 128) {
        int t = NTOK + i / 12, rem = i % 12, z = rem >> 2, seg = rem & 3;
        __nv_bfloat16* dst = (z == 0 ? sq : z == 1 ? sk : sv) + t * AS + seg * 8;
        *(uint4*)dst = make_uint4(0, 0, 0, 0);
    }
    for (int i = tid; i < 169; i += 128) sb[i] = rpb[i * 4 + h];
    __syncthreads();

    uint32_t squ = smem_u32(sq), sku = smem_u32(sk), svu = smem_u32(sv);
    uint32_t aBase = squ + (uint32_t)((wq * 16 + ((mi & 1) << 3) + l7) * 20 +
                                      ((mi >> 1) << 2)) * 4;
    uint32_t bBase[4];
    #pragma unroll
    for (int np = 0; np < 4; np++)
        bBase[np] = sku + (uint32_t)((np * 16 + ((mi >> 1) << 3) + l7) * 20 +
                                     ((mi & 1) << 2)) * 4;

    // QK^T: warp computes rows [16wq, 16wq+16) x 64 cols
    float acc[8][4];
    #pragma unroll
    for (int na = 0; na < 8; na++)
        #pragma unroll
        for (int q2 = 0; q2 < 4; q2++) acc[na][q2] = 0.0f;
    #pragma unroll
    for (int kt = 0; kt < 2; kt++) {
        uint32_t a[4], bb[8][2];
        asm volatile("ldmatrix.sync.aligned.m8n8.x4.shared.b16 {%0,%1,%2,%3}, [%4];"
                     : "=r"(a[0]), "=r"(a[1]), "=r"(a[2]), "=r"(a[3])
                     : "r"(aBase + kt * 32));
        #pragma unroll
        for (int np = 0; np < 4; np++)
            asm volatile("ldmatrix.sync.aligned.m8n8.x4.shared.b16 {%0,%1,%2,%3}, [%4];"
                         : "=r"(bb[2*np][0]), "=r"(bb[2*np][1]),
                           "=r"(bb[2*np+1][0]), "=r"(bb[2*np+1][1])
                         : "r"(bBase[np] + kt * 32));
        #pragma unroll
        for (int na = 0; na < 8; na++)
            asm volatile(
                "mma.sync.aligned.m16n8k16.row.col.f32.bf16.bf16.f32 "
                "{%0,%1,%2,%3}, {%4,%5,%6,%7}, {%8,%9}, {%0,%1,%2,%3};"
                : "+f"(acc[na][0]), "+f"(acc[na][1]), "+f"(acc[na][2]), "+f"(acc[na][3])
                : "r"(a[0]), "r"(a[1]), "r"(a[2]), "r"(a[3]),
                  "r"(bb[na][0]), "r"(bb[na][1]));
    }

    // bias + mask + softmax (rows n1 = 16wq+g, n2 = n1+8)
    int wi = w & 63, wy = wi >> 3, wx = wi & 7;
    const float scale = 0.17677669529663687f;
    #pragma unroll
    for (int rb = 0; rb < 2; rb++) {
        int n = wq * 16 + rb * 8 + g;
        bool nvalid = n < NTOK;
        int iy = n / WS, ix = n - iy * WS;
        int rn = nvalid ? region_of(wy * WS + iy) * 3 + region_of(wx * WS + ix) : 0;
        float mx = -1e30f;
        #pragma unroll
        for (int na = 0; na < 8; na++)
            #pragma unroll
            for (int j = 0; j < 2; j++) {
                int m = 8 * na + 2 * cq + j;
                float s;
                if (m < NTOK) {
                    if (nvalid) {
                        int jy = m / WS, jx = m - jy * WS;
                        int rel = (iy - jy + WS - 1) * (2 * WS - 1) + (ix - jx + WS - 1);
                        s = acc[na][2 * rb + j] * scale + sb[rel];
                        int rm = region_of(wy * WS + jy) * 3 + region_of(wx * WS + jx);
                        if (rn != rm) s -= 100.0f;
                    } else s = 0.0f;
                } else s = -30000.0f;
                acc[na][2 * rb + j] = s;
                mx = fmaxf(mx, s);
            }
        mx = fmaxf(mx, __shfl_xor_sync(0xffffffffu, mx, 1));
        mx = fmaxf(mx, __shfl_xor_sync(0xffffffffu, mx, 2));
        float sum = 0.0f;
        #pragma unroll
        for (int na = 0; na < 8; na++)
            #pragma unroll
            for (int j = 0; j < 2; j++) {
                float e = __expf(acc[na][2 * rb + j] - mx);
                acc[na][2 * rb + j] = e;
                sum += e;
            }
        sum += __shfl_xor_sync(0xffffffffu, sum, 1);
        sum += __shfl_xor_sync(0xffffffffu, sum, 2);
        float inv = 1.0f / sum;
        #pragma unroll
        for (int na = 0; na < 8; na++)
            #pragma unroll
            for (int j = 0; j < 2; j++) acc[na][2 * rb + j] *= inv;
    }

    // PV: probs (regs, bf16-packed as A) x V^T (ldmatrix.trans as B)
    float acc2[4][4];
    #pragma unroll
    for (int nd = 0; nd < 4; nd++)
        #pragma unroll
        for (int q2 = 0; q2 < 4; q2++) acc2[nd][q2] = 0.0f;
    #pragma unroll
    for (int kt = 0; kt < 4; kt++) {
        uint32_t aP[4];
        __nv_bfloat162 p0 = __floats2bfloat162_rn(acc[2*kt][0],   acc[2*kt][1]);
        __nv_bfloat162 p1 = __floats2bfloat162_rn(acc[2*kt][2],   acc[2*kt][3]);
        __nv_bfloat162 p2 = __floats2bfloat162_rn(acc[2*kt+1][0], acc[2*kt+1][1]);
        __nv_bfloat162 p3 = __floats2bfloat162_rn(acc[2*kt+1][2], acc[2*kt+1][3]);
        aP[0] = *reinterpret_cast<uint32_t*>(&p0);
        aP[1] = *reinterpret_cast<uint32_t*>(&p1);
        aP[2] = *reinterpret_cast<uint32_t*>(&p2);
        aP[3] = *reinterpret_cast<uint32_t*>(&p3);
        uint32_t bv[4][2];
        #pragma unroll
        for (int dp = 0; dp < 2; dp++) {
            uint32_t addr = svu +
                (uint32_t)((16 * kt + ((mi & 1) << 3) + l7) * 20) * 4 +
                (uint32_t)((16 * dp + ((mi >> 1) << 3)) * 2);
            asm volatile("ldmatrix.sync.aligned.m8n8.x4.trans.shared.b16 {%0,%1,%2,%3}, [%4];"
                         : "=r"(bv[2*dp][0]), "=r"(bv[2*dp][1]),
                           "=r"(bv[2*dp+1][0]), "=r"(bv[2*dp+1][1])
                         : "r"(addr));
        }
        #pragma unroll
        for (int nd = 0; nd < 4; nd++)
            asm volatile(
                "mma.sync.aligned.m16n8k16.row.col.f32.bf16.bf16.f32 "
                "{%0,%1,%2,%3}, {%4,%5,%6,%7}, {%8,%9}, {%0,%1,%2,%3};"
                : "+f"(acc2[nd][0]), "+f"(acc2[nd][1]), "+f"(acc2[nd][2]), "+f"(acc2[nd][3])
                : "r"(aP[0]), "r"(aP[1]), "r"(aP[2]), "r"(aP[3]),
                  "r"(bv[nd][0]), "r"(bv[nd][1]));
    }

    // store rows < 49
    #pragma unroll
    for (int rb = 0; rb < 2; rb++) {
        int n = wq * 16 + rb * 8 + g;
        if (n < NTOK) {
            #pragma unroll
            for (int nd = 0; nd < 4; nd++) {
                __nv_bfloat162 o = __floats2bfloat162_rn(acc2[nd][2*rb], acc2[nd][2*rb+1]);
                *(__nv_bfloat162*)(&g_attn[(size_t)(w * NTOK + n) * DIM + h * HD +
                                           8 * nd + 2 * cq]) = o;
            }
        }
    }
}

// ------------------------------- launcher ------------------------------------
extern "C" void kernel_launch(void* const* d_in, const int* in_sizes, int n_in,
                              void* d_out, int out_size) {
    const float* x      = (const float*)d_in[0];
    const float* qkv_w  = (const float*)d_in[1];
    const float* qkv_b  = (const float*)d_in[2];
    const float* proj_w = (const float*)d_in[3];
    const float* proj_b = (const float*)d_in[4];
    const float* rpb    = (const float*)d_in[5];
    const float* n1w    = (const float*)d_in[6];
    const float* n1b    = (const float*)d_in[7];
    const float* n2w    = (const float*)d_in[8];
    const float* n2b    = (const float*)d_in[9];
    const float* w1     = (const float*)d_in[10];
    const float* b1     = (const float*)d_in[11];
    const float* w2     = (const float*)d_in[12];
    const float* b2     = (const float*)d_in[13];
    float* out = (float*)d_out;

    __nv_bfloat16 *p_xw, *p_qkv, *p_attn, *p_ln2, *p_h, *p_wtq, *p_wtp, *p_wt1, *p_wt2;
    float *p_x2;
    cudaGetSymbolAddress((void**)&p_xw,   g_xw);
    cudaGetSymbolAddress((void**)&p_qkv,  g_qkv);
    cudaGetSymbolAddress((void**)&p_attn, g_attn);
    cudaGetSymbolAddress((void**)&p_x2,   g_x2);
    cudaGetSymbolAddress((void**)&p_ln2,  g_ln2);
    cudaGetSymbolAddress((void**)&p_h,    g_h);
    cudaGetSymbolAddress((void**)&p_wtq,  g_wt_qkv);
    cudaGetSymbolAddress((void**)&p_wtp,  g_wt_proj);
    cudaGetSymbolAddress((void**)&p_wt1,  g_wt1);
    cudaGetSymbolAddress((void**)&p_wt2,  g_wt2);

    // 0) fused weight transposes
    k_transpose_all<<<768, 256>>>(qkv_w, proj_w, w1, w2);

    // 1) LN1 + shift + window partition
    k_ln_shift_part<<<MTOK, 128>>>(x, n1w, n1b);

    // 2) QKV GEMM -> bf16
    k_bgemm<0><<<dim3(3, MTOK / 128), 256>>>(p_xw, p_wtq, qkv_b, nullptr, p_qkv,
                                             128, 384, nullptr, nullptr, nullptr);

    // 3) tensor-core windowed attention -> bf16
    k_attn<<<dim3(NWIN, HEADS), 128>>>(p_qkv, rpb);

    // 4) proj GEMM + residual + window-reverse + LN2 (fused)
    k_bgemm<3><<<dim3(1, MTOK / 128), 256>>>(p_attn, p_wtp, proj_b, x, p_ln2,
                                             128, 128, n2w, n2b, p_x2);

    // 5) MLP1 + GELU -> bf16
    k_bgemm<1><<<dim3(4, MTOK / 128), 256>>>(p_ln2, p_wt1, b1, nullptr, p_h,
                                             128, 512, nullptr, nullptr, nullptr);

    // 6) MLP2 + bias + residual -> d_out fp32
    k_bgemm<2><<<dim3(1, MTOK / 128), 256>>>(p_h, p_wt2, b2, p_x2, out,
                                             512, 128, nullptr, nullptr, nullptr);
}

// round 8
// speedup vs baseline: 5.4378x; 1.2257x over previous
#include <cuda_runtime.h>
#include <cuda_bf16.h>
#include <math.h>
#include <stdint.h>

#define Himg 56
#define Wimg 56
#define WS 7
#define SHIFT 3
#define HEADS 4
#define DIM 128
#define NTOK 49
#define NWIN 4096           // 64 imgs * 64 windows
#define MTOK 200704         // NWIN * NTOK
#define HD 32

// ---------------- scratch (static device globals; no allocation) -------------
__device__ __nv_bfloat16 g_xw  [(size_t)MTOK * DIM];
__device__ __nv_bfloat16 g_qkv [(size_t)MTOK * 3 * DIM];
__device__ __nv_bfloat16 g_attn[(size_t)MTOK * DIM];
__device__ float         g_x2  [(size_t)MTOK * DIM];
__device__ __nv_bfloat16 g_ln2 [(size_t)MTOK * DIM];
__device__ __nv_bfloat16 g_h   [(size_t)MTOK * 4 * DIM];
// transposed weights [N, K] in bf16
__device__ __nv_bfloat16 g_wt_qkv [384 * 128];
__device__ __nv_bfloat16 g_wt_proj[128 * 128];
__device__ __nv_bfloat16 g_wt1    [512 * 128];
__device__ __nv_bfloat16 g_wt2    [128 * 512];

__device__ __forceinline__ uint32_t smem_u32(const void* p) {
    uint32_t a;
    asm("{ .reg .u64 t; cvta.to.shared.u64 t, %1; cvt.u32.u64 %0, t; }" : "=r"(a) : "l"(p));
    return a;
}
__device__ __forceinline__ void cpa16(uint32_t dst, const void* src) {
    asm volatile("cp.async.cg.shared.global [%0], [%1], 16;" :: "r"(dst), "l"(src));
}
__device__ __forceinline__ int img_of(int wt) {
    int w = wt / NTOK, n = wt - w * NTOK;
    int bimg = w >> 6, wi = w & 63;
    int rr = (wi >> 3) * WS + n / WS;
    int cc = (wi & 7)  * WS + n % WS;
    int r = rr + SHIFT; if (r >= Himg) r -= Himg;
    int c = cc + SHIFT; if (c >= Wimg) c -= Wimg;
    return bimg * 3136 + r * 56 + c;
}

// ---------------- kernel 0: all 4 weight transposes fused ---------------------
__global__ void k_transpose_all(const float* __restrict__ qkv_w,
                                const float* __restrict__ proj_w,
                                const float* __restrict__ w1,
                                const float* __restrict__ w2) {
    int i = blockIdx.x * 256 + threadIdx.x;
    if (i < 49152) {
        int k = i / 384, n = i - k * 384;
        g_wt_qkv[n * 128 + k] = __float2bfloat16(qkv_w[i]);
    } else if (i < 65536) {
        int j = i - 49152;
        int k = j >> 7, n = j & 127;
        g_wt_proj[n * 128 + k] = __float2bfloat16(proj_w[j]);
    } else if (i < 131072) {
        int j = i - 65536;
        int k = j >> 9, n = j & 511;
        g_wt1[n * 128 + k] = __float2bfloat16(w1[j]);
    } else if (i < 196608) {
        int j = i - 131072;
        int k = j >> 7, n = j & 127;
        g_wt2[n * 512 + k] = __float2bfloat16(w2[j]);
    }
}

// ---------------- kernel 1: LN1 + shift + partition (warp per token) ---------
__global__ void __launch_bounds__(256)
k_ln_shift_part(const float* __restrict__ x,
                const float* __restrict__ gw,
                const float* __restrict__ gb) {
    int warp = threadIdx.x >> 5, lane = threadIdx.x & 31;
    int t = blockIdx.x * 8 + warp;
    int win = t / NTOK, n = t - win * NTOK;
    int bimg = win >> 6, wi = win & 63;
    int rr = (wi >> 3) * WS + n / WS;
    int cc = (wi & 7)  * WS + n % WS;
    int r = rr + SHIFT; if (r >= Himg) r -= Himg;
    int c = cc + SHIFT; if (c >= Wimg) c -= Wimg;
    const float4 v4 = *(const float4*)(x + ((size_t)bimg * 3136 + r * 56 + c) * DIM + lane * 4);
    float sv = v4.x + v4.y + v4.z + v4.w;
    float sq = v4.x * v4.x + v4.y * v4.y + v4.z * v4.z + v4.w * v4.w;
    #pragma unroll
    for (int o = 16; o > 0; o >>= 1) {
        sv += __shfl_xor_sync(0xffffffffu, sv, o);
        sq += __shfl_xor_sync(0xffffffffu, sq, o);
    }
    float mean = sv * (1.0f / 128.0f);
    float inv  = rsqrtf(sq * (1.0f / 128.0f) - mean * mean + 1e-5f);
    float4 w4 = *(const float4*)(gw + lane * 4);
    float4 b4 = *(const float4*)(gb + lane * 4);
    __nv_bfloat162 o0 = __floats2bfloat162_rn((v4.x - mean) * inv * w4.x + b4.x,
                                              (v4.y - mean) * inv * w4.y + b4.y);
    __nv_bfloat162 o1 = __floats2bfloat162_rn((v4.z - mean) * inv * w4.z + b4.z,
                                              (v4.w - mean) * inv * w4.w + b4.w);
    uint2 pk;
    pk.x = *reinterpret_cast<uint32_t*>(&o0);
    pk.y = *reinterpret_cast<uint32_t*>(&o1);
    *(uint2*)(g_xw + (size_t)t * DIM + lane * 4) = pk;
}

// -------- bf16 HMMA GEMM, dynamic smem, KCP-chunked, 128x128 tile ------------
// EPI: 0 = +bias (bf16 out); 1 = +bias, GELU (bf16 out);
//      2 = +bias +residual (fp32 out);
//      3 = +bias +residual[x, scattered] + LN2 -> ln2 bf16 (Cout) + x2 fp32 (out2)
template <int EPI, int KCP, int NBUF>
__global__ void __launch_bounds__(256, 2)
k_bgemm(const __nv_bfloat16* __restrict__ A, const __nv_bfloat16* __restrict__ BT,
        const float* __restrict__ bias, const float* __restrict__ res,
        void* __restrict__ Cout, int K, int N,
        const float* __restrict__ lnw, const float* __restrict__ lnb,
        float* __restrict__ out2) {
    constexpr int SROWP = KCP / 2 + 4;         // words per smem row (4r mod 32 -> conflict-free)
    constexpr int BUFWP = 128 * SROWP;
    constexpr int KSTEP = KCP / 16;
    constexpr int HW = KCP / 4;                // words per half-row
    extern __shared__ uint32_t dsm[];
    uint32_t* sAp = dsm;
    uint32_t* sBp = dsm + NBUF * BUFWP;
    float* redS = (float*)(dsm + 2 * NBUF * BUFWP);
    float* redQ = redS + 256;

    int tid = threadIdx.x;
    int wid = tid >> 5, lane = tid & 31;
    int wm = wid & 3, wn = wid >> 2;
    int m0 = blockIdx.y << 7, n0 = blockIdx.x << 7;
    int g = lane >> 2, cq = lane & 3;
    int mi = lane >> 3, l7 = lane & 7;

    float acc[2][8][4];
    #pragma unroll
    for (int i = 0; i < 2; i++)
        #pragma unroll
        for (int j = 0; j < 8; j++)
            #pragma unroll
            for (int q = 0; q < 4; q++) acc[i][j][q] = 0.0f;

    uint32_t sAu = smem_u32(sAp), sBu = smem_u32(sBp);
    int ROWT = tid >> 1, HALF = tid & 1;
    const __nv_bfloat16* Asrc = A  + (size_t)(m0 + ROWT) * K + HALF * (KCP / 2);
    const __nv_bfloat16* Bsrc = BT + (size_t)(n0 + ROWT) * K + HALF * (KCP / 2);
    uint32_t Adst = sAu + (ROWT * SROWP + HALF * HW) * 4;
    uint32_t Bdst = sBu + (ROWT * SROWP + HALF * HW) * 4;

    uint32_t aRow[2];
    #pragma unroll
    for (int ma = 0; ma < 2; ma++)
        aRow[ma] = (uint32_t)((wm * 32 + ma * 16 + ((mi & 1) << 3) + l7) * SROWP +
                              ((mi >> 1) << 2)) * 4;
    uint32_t bRow[4];
    #pragma unroll
    for (int np = 0; np < 4; np++)
        bRow[np] = (uint32_t)((wn * 64 + np * 16 + ((mi >> 1) << 3) + l7) * SROWP +
                              ((mi & 1) << 2)) * 4;

#define LOAD_CHUNK(ch, b)                                                     \
    {                                                                         \
        _Pragma("unroll")                                                     \
        for (int i_ = 0; i_ < HW / 4; i_++) {                                 \
            cpa16(Adst + (b) * BUFWP * 4 + i_ * 16, Asrc + (ch) * KCP + i_ * 8); \
            cpa16(Bdst + (b) * BUFWP * 4 + i_ * 16, Bsrc + (ch) * KCP + i_ * 8); \
        }                                                                     \
        asm volatile("cp.async.commit_group;" ::: "memory");                  \
    }

#define COMPUTE(b)                                                            \
    {                                                                         \
        uint32_t baseA = sAu + (b) * BUFWP * 4;                               \
        uint32_t baseB = sBu + (b) * BUFWP * 4;                               \
        _Pragma("unroll")                                                     \
        for (int ks = 0; ks < KSTEP; ks++) {                                  \
            uint32_t kwb = (uint32_t)ks * 32;                                 \
            uint32_t a_[2][4], bb_[8][2];                                     \
            _Pragma("unroll")                                                 \
            for (int ma = 0; ma < 2; ma++)                                    \
                asm volatile(                                                 \
                    "ldmatrix.sync.aligned.m8n8.x4.shared.b16 {%0,%1,%2,%3}, [%4];" \
                    : "=r"(a_[ma][0]), "=r"(a_[ma][1]), "=r"(a_[ma][2]), "=r"(a_[ma][3]) \
                    : "r"(baseA + aRow[ma] + kwb));                           \
            _Pragma("unroll")                                                 \
            for (int np = 0; np < 4; np++)                                    \
                asm volatile(                                                 \
                    "ldmatrix.sync.aligned.m8n8.x4.shared.b16 {%0,%1,%2,%3}, [%4];" \
                    : "=r"(bb_[2*np][0]), "=r"(bb_[2*np][1]),                 \
                      "=r"(bb_[2*np+1][0]), "=r"(bb_[2*np+1][1])              \
                    : "r"(baseB + bRow[np] + kwb));                           \
            _Pragma("unroll")                                                 \
            for (int ma = 0; ma < 2; ma++)                                    \
                _Pragma("unroll")                                             \
                for (int na = 0; na < 8; na++)                                \
                    asm volatile(                                             \
                        "mma.sync.aligned.m16n8k16.row.col.f32.bf16.bf16.f32 " \
                        "{%0,%1,%2,%3}, {%4,%5,%6,%7}, {%8,%9}, {%0,%1,%2,%3};" \
                        : "+f"(acc[ma][na][0]), "+f"(acc[ma][na][1]),         \
                          "+f"(acc[ma][na][2]), "+f"(acc[ma][na][3])          \
                        : "r"(a_[ma][0]), "r"(a_[ma][1]), "r"(a_[ma][2]), "r"(a_[ma][3]), \
                          "r"(bb_[na][0]), "r"(bb_[na][1]));                  \
        }                                                                     \
    }

    if (NBUF == 1) {
        LOAD_CHUNK(0, 0);
        asm volatile("cp.async.wait_group 0;" ::: "memory");
        __syncthreads();
        COMPUTE(0);
    } else {
        int nch = K / KCP;
        LOAD_CHUNK(0, 0);
        for (int ch = 0; ch < nch; ch++) {
            if (ch + 1 < nch) {
                LOAD_CHUNK(ch + 1, (ch + 1) & 1);
                asm volatile("cp.async.wait_group 1;" ::: "memory");
            } else {
                asm volatile("cp.async.wait_group 0;" ::: "memory");
            }
            __syncthreads();
            COMPUTE(ch & 1);
            __syncthreads();
        }
    }
#undef LOAD_CHUNK
#undef COMPUTE

    if (EPI == 3) {
        int tok[2][2];
        #pragma unroll
        for (int ma = 0; ma < 2; ma++) {
            int rA = m0 + wm * 32 + ma * 16 + g;
            tok[ma][0] = img_of(rA);
            tok[ma][1] = img_of(rA + 8);
        }
        float sum[2][2] = {}, sq[2][2] = {};
        #pragma unroll
        for (int ma = 0; ma < 2; ma++)
            #pragma unroll
            for (int na = 0; na < 8; na++) {
                int cb = n0 + wn * 64 + na * 8 + 2 * cq;
                float b0 = bias[cb], b1 = bias[cb + 1];
                float2 rA2 = *(const float2*)(res + (size_t)tok[ma][0] * DIM + cb);
                float2 rB2 = *(const float2*)(res + (size_t)tok[ma][1] * DIM + cb);
                float v0 = acc[ma][na][0] + b0 + rA2.x;
                float v1 = acc[ma][na][1] + b1 + rA2.y;
                float v2 = acc[ma][na][2] + b0 + rB2.x;
                float v3 = acc[ma][na][3] + b1 + rB2.y;
                acc[ma][na][0] = v0; acc[ma][na][1] = v1;
                acc[ma][na][2] = v2; acc[ma][na][3] = v3;
                sum[ma][0] += v0 + v1;  sq[ma][0] += v0 * v0 + v1 * v1;
                sum[ma][1] += v2 + v3;  sq[ma][1] += v2 * v2 + v3 * v3;
            }
        #pragma unroll
        for (int ma = 0; ma < 2; ma++)
            #pragma unroll
            for (int rb = 0; rb < 2; rb++) {
                sum[ma][rb] += __shfl_xor_sync(0xffffffffu, sum[ma][rb], 1);
                sum[ma][rb] += __shfl_xor_sync(0xffffffffu, sum[ma][rb], 2);
                sq[ma][rb]  += __shfl_xor_sync(0xffffffffu, sq[ma][rb], 1);
                sq[ma][rb]  += __shfl_xor_sync(0xffffffffu, sq[ma][rb], 2);
            }
        if (cq == 0) {
            #pragma unroll
            for (int ma = 0; ma < 2; ma++)
                #pragma unroll
                for (int rb = 0; rb < 2; rb++) {
                    int rr = wm * 32 + ma * 16 + rb * 8 + g;
                    redS[wn * 128 + rr] = sum[ma][rb];
                    redQ[wn * 128 + rr] = sq[ma][rb];
                }
        }
        __syncthreads();
        float mean[2][2], inv[2][2];
        #pragma unroll
        for (int ma = 0; ma < 2; ma++)
            #pragma unroll
            for (int rb = 0; rb < 2; rb++) {
                int rr = wm * 32 + ma * 16 + rb * 8 + g;
                float ts = redS[rr] + redS[128 + rr];
                float tq = redQ[rr] + redQ[128 + rr];
                float mn = ts * (1.0f / 128.0f);
                float vr = tq * (1.0f / 128.0f) - mn * mn;
                mean[ma][rb] = mn;
                inv[ma][rb] = rsqrtf(vr + 1e-5f);
            }
        __nv_bfloat16* Cb = (__nv_bfloat16*)Cout;
        #pragma unroll
        for (int ma = 0; ma < 2; ma++)
            #pragma unroll
            for (int na = 0; na < 8; na++) {
                int cb = n0 + wn * 64 + na * 8 + 2 * cq;
                float w0 = lnw[cb], w1 = lnw[cb + 1];
                float e0 = lnb[cb], e1 = lnb[cb + 1];
                #pragma unroll
                for (int rb = 0; rb < 2; rb++) {
                    int ti = tok[ma][rb];
                    float v0 = acc[ma][na][2 * rb], v1 = acc[ma][na][2 * rb + 1];
                    *(float2*)(out2 + (size_t)ti * DIM + cb) = make_float2(v0, v1);
                    float l0 = (v0 - mean[ma][rb]) * inv[ma][rb] * w0 + e0;
                    float l1 = (v1 - mean[ma][rb]) * inv[ma][rb] * w1 + e1;
                    *(__nv_bfloat162*)(Cb + (size_t)ti * DIM + cb) =
                        __floats2bfloat162_rn(l0, l1);
                }
            }
        return;
    }

    #pragma unroll
    for (int ma = 0; ma < 2; ma++) {
        int r0 = m0 + wm * 32 + ma * 16 + g;
        #pragma unroll
        for (int na = 0; na < 8; na++) {
            int cb = n0 + wn * 64 + na * 8 + 2 * cq;
            float b0 = bias[cb], b1 = bias[cb + 1];
            float v0 = acc[ma][na][0] + b0;
            float v1 = acc[ma][na][1] + b1;
            float v2 = acc[ma][na][2] + b0;
            float v3 = acc[ma][na][3] + b1;
            if (EPI == 1) {
                v0 = 0.5f * v0 * (1.0f + erff(v0 * 0.7071067811865476f));
                v1 = 0.5f * v1 * (1.0f + erff(v1 * 0.7071067811865476f));
                v2 = 0.5f * v2 * (1.0f + erff(v2 * 0.7071067811865476f));
                v3 = 0.5f * v3 * (1.0f + erff(v3 * 0.7071067811865476f));
            }
            if (EPI == 0 || EPI == 1) {
                __nv_bfloat16* Cb = (__nv_bfloat16*)Cout;
                *(__nv_bfloat162*)(Cb + (size_t)r0 * N + cb) =
                    __floats2bfloat162_rn(v0, v1);
                *(__nv_bfloat162*)(Cb + (size_t)(r0 + 8) * N + cb) =
                    __floats2bfloat162_rn(v2, v3);
            } else {
                float2 r1v = *(const float2*)(res + (size_t)r0 * N + cb);
                float2 r2v = *(const float2*)(res + (size_t)(r0 + 8) * N + cb);
                v0 += r1v.x; v1 += r1v.y; v2 += r2v.x; v3 += r2v.y;
                float* Cf = (float*)Cout;
                *(float2*)(Cf + (size_t)r0 * N + cb)       = make_float2(v0, v1);
                *(float2*)(Cf + (size_t)(r0 + 8) * N + cb) = make_float2(v2, v3);
            }
        }
    }
}

// ---------------- kernel 3: tensor-core windowed attention -------------------
#define AS 40   // bf16 row stride (= 20 words, conflict-free, 16B-aligned rows)

__global__ void __launch_bounds__(128)
k_attn(const __nv_bfloat16* __restrict__ qkv, const float* __restrict__ rpb) {
    __shared__ __align__(16) __nv_bfloat16 sq[64 * AS], sk[64 * AS], sv[64 * AS];
    __shared__ float sb[169];
    int w = blockIdx.x, h = blockIdx.y;
    int tid = threadIdx.x, wq = tid >> 5, lane = tid & 31;
    int g = lane >> 2, cq = lane & 3;
    int mi = lane >> 3, l7 = lane & 7;

    for (int i = tid; i < NTOK * 12; i += 128) {
        int t = i / 12, rem = i - t * 12, z = rem >> 2, seg = rem & 3;
        const uint4* src = (const uint4*)(qkv + (size_t)(w * NTOK + t) * 384 +
                                          z * 128 + h * 32 + seg * 8);
        __nv_bfloat16* dst = (z == 0 ? sq : z == 1 ? sk : sv) + t * AS + seg * 8;
        *(uint4*)dst = *src;
    }
    for (int i = tid; i < 15 * 12; i += 128) {
        int t = NTOK + i / 12, rem = i % 12, z = rem >> 2, seg = rem & 3;
        __nv_bfloat16* dst = (z == 0 ? sq : z == 1 ? sk : sv) + t * AS + seg * 8;
        *(uint4*)dst = make_uint4(0, 0, 0, 0);
    }
    for (int i = tid; i < 169; i += 128) sb[i] = rpb[i * 4 + h];
    __syncthreads();

    uint32_t squ = smem_u32(sq), sku = smem_u32(sk), svu = smem_u32(sv);
    uint32_t aBase = squ + (uint32_t)((wq * 16 + ((mi & 1) << 3) + l7) * 20 +
                                      ((mi >> 1) << 2)) * 4;
    uint32_t bBase[4];
    #pragma unroll
    for (int np = 0; np < 4; np++)
        bBase[np] = sku + (uint32_t)((np * 16 + ((mi >> 1) << 3) + l7) * 20 +
                                     ((mi & 1) << 2)) * 4;

    // QK^T
    float acc[8][4];
    #pragma unroll
    for (int na = 0; na < 8; na++)
        #pragma unroll
        for (int q2 = 0; q2 < 4; q2++) acc[na][q2] = 0.0f;
    #pragma unroll
    for (int kt = 0; kt < 2; kt++) {
        uint32_t a[4], bb[8][2];
        asm volatile("ldmatrix.sync.aligned.m8n8.x4.shared.b16 {%0,%1,%2,%3}, [%4];"
                     : "=r"(a[0]), "=r"(a[1]), "=r"(a[2]), "=r"(a[3])
                     : "r"(aBase + kt * 32));
        #pragma unroll
        for (int np = 0; np < 4; np++)
            asm volatile("ldmatrix.sync.aligned.m8n8.x4.shared.b16 {%0,%1,%2,%3}, [%4];"
                         : "=r"(bb[2*np][0]), "=r"(bb[2*np][1]),
                           "=r"(bb[2*np+1][0]), "=r"(bb[2*np+1][1])
                         : "r"(bBase[np] + kt * 32));
        #pragma unroll
        for (int na = 0; na < 8; na++)
            asm volatile(
                "mma.sync.aligned.m16n8k16.row.col.f32.bf16.bf16.f32 "
                "{%0,%1,%2,%3}, {%4,%5,%6,%7}, {%8,%9}, {%0,%1,%2,%3};"
                : "+f"(acc[na][0]), "+f"(acc[na][1]), "+f"(acc[na][2]), "+f"(acc[na][3])
                : "r"(a[0]), "r"(a[1]), "r"(a[2]), "r"(a[3]),
                  "r"(bb[na][0]), "r"(bb[na][1]));
    }

    // bias + mask + softmax -- rel = f(n) - f(m) + 84 decomposition
    int wi = w & 63, wy = wi >> 3, wx = wi & 7;
    bool ey = (wy == 7), ex = (wx == 7);
    const float scale = 0.17677669529663687f;
    int fm[14], rmv[14];
    #pragma unroll
    for (int na = 0; na < 7; na++)
        #pragma unroll
        for (int j = 0; j < 2; j++) {
            int m = 8 * na + 2 * cq + j;
            int mm = m < NTOK ? m : 0;
            int jy = mm / WS, jx = mm - jy * WS;
            fm[na * 2 + j] = jy * 13 + jx;
            int ry = ey ? (jy < 4 ? 1 : 2) : 0;
            int rx = ex ? (jx < 4 ? 1 : 2) : 0;
            rmv[na * 2 + j] = ry * 3 + rx;
        }
    bool v6 = (cq == 0);      // na==6 column valid only when m==48

    #pragma unroll
    for (int rb = 0; rb < 2; rb++) {
        int n = wq * 16 + rb * 8 + g;
        int nc = n < NTOK ? n : 0;
        int iy = nc / WS, ix = nc - iy * WS;
        int fn = iy * 13 + ix + 84;
        int rn = (ey ? (iy < 4 ? 1 : 2) : 0) * 3 + (ex ? (ix < 4 ? 1 : 2) : 0);
        float mx = -1e30f;
        #pragma unroll
        for (int na = 0; na < 8; na++)
            #pragma unroll
            for (int j = 0; j < 2; j++) {
                float s;
                if (na == 7) {
                    s = -30000.0f;
                } else {
                    int idx = na * 2 + j;
                    s = fmaf(acc[na][2 * rb + j], scale, sb[fn - fm[idx]]);
                    if (rn != rmv[idx]) s -= 100.0f;
                    if (na == 6 && !(v6 && j == 0)) s = -30000.0f;
                }
                acc[na][2 * rb + j] = s;
                mx = fmaxf(mx, s);
            }
        mx = fmaxf(mx, __shfl_xor_sync(0xffffffffu, mx, 1));
        mx = fmaxf(mx, __shfl_xor_sync(0xffffffffu, mx, 2));
        float sum = 0.0f;
        #pragma unroll
        for (int na = 0; na < 8; na++)
            #pragma unroll
            for (int j = 0; j < 2; j++) {
                float e = __expf(acc[na][2 * rb + j] - mx);
                acc[na][2 * rb + j] = e;
                sum += e;
            }
        sum += __shfl_xor_sync(0xffffffffu, sum, 1);
        sum += __shfl_xor_sync(0xffffffffu, sum, 2);
        float inv = 1.0f / sum;
        #pragma unroll
        for (int na = 0; na < 8; na++)
            #pragma unroll
            for (int j = 0; j < 2; j++) acc[na][2 * rb + j] *= inv;
    }

    // PV
    float acc2[4][4];
    #pragma unroll
    for (int nd = 0; nd < 4; nd++)
        #pragma unroll
        for (int q2 = 0; q2 < 4; q2++) acc2[nd][q2] = 0.0f;
    #pragma unroll
    for (int kt = 0; kt < 4; kt++) {
        uint32_t aP[4];
        __nv_bfloat162 p0 = __floats2bfloat162_rn(acc[2*kt][0],   acc[2*kt][1]);
        __nv_bfloat162 p1 = __floats2bfloat162_rn(acc[2*kt][2],   acc[2*kt][3]);
        __nv_bfloat162 p2 = __floats2bfloat162_rn(acc[2*kt+1][0], acc[2*kt+1][1]);
        __nv_bfloat162 p3 = __floats2bfloat162_rn(acc[2*kt+1][2], acc[2*kt+1][3]);
        aP[0] = *reinterpret_cast<uint32_t*>(&p0);
        aP[1] = *reinterpret_cast<uint32_t*>(&p1);
        aP[2] = *reinterpret_cast<uint32_t*>(&p2);
        aP[3] = *reinterpret_cast<uint32_t*>(&p3);
        uint32_t bv[4][2];
        #pragma unroll
        for (int dp = 0; dp < 2; dp++) {
            uint32_t addr = svu +
                (uint32_t)((16 * kt + ((mi & 1) << 3) + l7) * 20) * 4 +
                (uint32_t)((16 * dp + ((mi >> 1) << 3)) * 2);
            asm volatile("ldmatrix.sync.aligned.m8n8.x4.trans.shared.b16 {%0,%1,%2,%3}, [%4];"
                         : "=r"(bv[2*dp][0]), "=r"(bv[2*dp][1]),
                           "=r"(bv[2*dp+1][0]), "=r"(bv[2*dp+1][1])
                         : "r"(addr));
        }
        #pragma unroll
        for (int nd = 0; nd < 4; nd++)
            asm volatile(
                "mma.sync.aligned.m16n8k16.row.col.f32.bf16.bf16.f32 "
                "{%0,%1,%2,%3}, {%4,%5,%6,%7}, {%8,%9}, {%0,%1,%2,%3};"
                : "+f"(acc2[nd][0]), "+f"(acc2[nd][1]), "+f"(acc2[nd][2]), "+f"(acc2[nd][3])
                : "r"(aP[0]), "r"(aP[1]), "r"(aP[2]), "r"(aP[3]),
                  "r"(bv[nd][0]), "r"(bv[nd][1]));
    }

    #pragma unroll
    for (int rb = 0; rb < 2; rb++) {
        int n = wq * 16 + rb * 8 + g;
        if (n < NTOK) {
            #pragma unroll
            for (int nd = 0; nd < 4; nd++) {
                __nv_bfloat162 o = __floats2bfloat162_rn(acc2[nd][2*rb], acc2[nd][2*rb+1]);
                *(__nv_bfloat162*)(&g_attn[(size_t)(w * NTOK + n) * DIM + h * HD +
                                           8 * nd + 2 * cq]) = o;
            }
        }
    }
}

// ------------------------------- launcher ------------------------------------
extern "C" void kernel_launch(void* const* d_in, const int* in_sizes, int n_in,
                              void* d_out, int out_size) {
    const float* x      = (const float*)d_in[0];
    const float* qkv_w  = (const float*)d_in[1];
    const float* qkv_b  = (const float*)d_in[2];
    const float* proj_w = (const float*)d_in[3];
    const float* proj_b = (const float*)d_in[4];
    const float* rpb    = (const float*)d_in[5];
    const float* n1w    = (const float*)d_in[6];
    const float* n1b    = (const float*)d_in[7];
    const float* n2w    = (const float*)d_in[8];
    const float* n2b    = (const float*)d_in[9];
    const float* w1     = (const float*)d_in[10];
    const float* b1     = (const float*)d_in[11];
    const float* w2     = (const float*)d_in[12];
    const float* b2     = (const float*)d_in[13];
    float* out = (float*)d_out;

    __nv_bfloat16 *p_xw, *p_qkv, *p_attn, *p_ln2, *p_h, *p_wtq, *p_wtp, *p_wt1, *p_wt2;
    float *p_x2;
    cudaGetSymbolAddress((void**)&p_xw,   g_xw);
    cudaGetSymbolAddress((void**)&p_qkv,  g_qkv);
    cudaGetSymbolAddress((void**)&p_attn, g_attn);
    cudaGetSymbolAddress((void**)&p_x2,   g_x2);
    cudaGetSymbolAddress((void**)&p_ln2,  g_ln2);
    cudaGetSymbolAddress((void**)&p_h,    g_h);
    cudaGetSymbolAddress((void**)&p_wtq,  g_wt_qkv);
    cudaGetSymbolAddress((void**)&p_wtp,  g_wt_proj);
    cudaGetSymbolAddress((void**)&p_wt1,  g_wt1);
    cudaGetSymbolAddress((void**)&p_wt2,  g_wt2);

    const size_t dyn1 = (size_t)(2 * 1 * 128 * 68 + 512) * 4;   // 71680 B (KCP=128, NBUF=1)
    const size_t dyn2 = (size_t)(2 * 2 * 128 * 36 + 512) * 4;   // 75776 B (KCP=64,  NBUF=2)
    cudaFuncSetAttribute(k_bgemm<0,128,1>, cudaFuncAttributeMaxDynamicSharedMemorySize, (int)dyn1);
    cudaFuncSetAttribute(k_bgemm<3,128,1>, cudaFuncAttributeMaxDynamicSharedMemorySize, (int)dyn1);
    cudaFuncSetAttribute(k_bgemm<1,128,1>, cudaFuncAttributeMaxDynamicSharedMemorySize, (int)dyn1);
    cudaFuncSetAttribute(k_bgemm<2,64,2>,  cudaFuncAttributeMaxDynamicSharedMemorySize, (int)dyn2);

    // 0) fused weight transposes
    k_transpose_all<<<768, 256>>>(qkv_w, proj_w, w1, w2);

    // 1) LN1 + shift + window partition (warp per token)
    k_ln_shift_part<<<MTOK / 8, 256>>>(x, n1w, n1b);

    // 2) QKV GEMM -> bf16
    k_bgemm<0,128,1><<<dim3(3, MTOK / 128), 256, dyn1>>>(p_xw, p_wtq, qkv_b, nullptr,
                                                         p_qkv, 128, 384, nullptr, nullptr, nullptr);

    // 3) tensor-core windowed attention -> bf16
    k_attn<<<dim3(NWIN, HEADS), 128>>>(p_qkv, rpb);

    // 4) proj GEMM + residual + window-reverse + LN2 (fused)
    k_bgemm<3,128,1><<<dim3(1, MTOK / 128), 256, dyn1>>>(p_attn, p_wtp, proj_b, x,
                                                         p_ln2, 128, 128, n2w, n2b, p_x2);

    // 5) MLP1 + GELU -> bf16
    k_bgemm<1,128,1><<<dim3(4, MTOK / 128), 256, dyn1>>>(p_ln2, p_wt1, b1, nullptr,
                                                         p_h, 128, 512, nullptr, nullptr, nullptr);

    // 6) MLP2 + bias + residual -> d_out fp32
    k_bgemm<2,64,2><<<dim3(1, MTOK / 128), 256, dyn2>>>(p_h, p_wt2, b2, p_x2,
                                                        out, 512, 128, nullptr, nullptr, nullptr);
}